// round 8
// baseline (speedup 1.0000x reference)
#include <cuda_runtime.h>
#include <cuda_bf16.h>
#include <cuda_fp16.h>
#include <math.h>
#include <stdint.h>

#define S_LEN   512
#define NBATCH  128
#define IN_DIM  512
#define HID     1024
#define GDIM    4096   // interleaved: col g -> gate g&3, unit g>>2
#define NOUT    4

// phase-1 tiling: 128x128 tiles, K-chunks of 32, 2-stage cp.async
#define BM 128
#define BN 128
#define BKK 32
#define KPAD 40        // fp16 row stride (80B)
#define NTHREADS 256

// recurrence: 128 CTAs = 2 row-halves x 64 col-tiles, each 64x64xK
#define PGRID 128
#define PTH 512
#define NCH 4                    // K chunks of 256
#define CHB 32768                // chunk: 64 rows x 512B
#define WB  131072               // W: 64 gate-cols x 2048B
#define OFF_W 0
#define OFF_A WB
#define DYN_B (WB + 3 * CHB)     // 229376

__device__ float  g_xp[(size_t)S_LEN * NBATCH * GDIM];
__device__ __half g_xh[(size_t)S_LEN * NBATCH * IN_DIM];
__device__ __half g_wih[(size_t)GDIM * IN_DIM];
__device__ float  g_bias[GDIM];
__device__ __half g_hh[2][NBATCH * HID];
__device__ int g_chcnt[NCH];     // per-chunk producer counters (monotone)

__device__ __forceinline__ unsigned su32(const void* p){
    return (unsigned)__cvta_generic_to_shared(p);
}
__device__ __forceinline__ float sigmoidf_(float x){ return 1.0f / (1.0f + expf(-x)); }
__device__ __forceinline__ void cpasync16(unsigned saddr, const void* g){
    asm volatile("cp.async.cg.shared.global [%0], [%1], 16;" :: "r"(saddr), "l"(g));
}
#define CP_COMMIT() asm volatile("cp.async.commit_group;")
#define CP_WAIT(n)  asm volatile("cp.async.wait_group %0;" :: "n"(n))

__device__ __forceinline__ void ldmx4(unsigned* r, unsigned addr){
    asm volatile("ldmatrix.sync.aligned.m8n8.x4.shared.b16 {%0,%1,%2,%3}, [%4];"
        : "=r"(r[0]), "=r"(r[1]), "=r"(r[2]), "=r"(r[3]) : "r"(addr));
}
__device__ __forceinline__ void mma_f16(float* d, const unsigned* a, const unsigned* b){
    asm volatile("mma.sync.aligned.m16n8k16.row.col.f32.f16.f16.f32 "
        "{%0,%1,%2,%3},{%4,%5,%6,%7},{%8,%9},{%0,%1,%2,%3};"
        : "+f"(d[0]), "+f"(d[1]), "+f"(d[2]), "+f"(d[3])
        : "r"(a[0]), "r"(a[1]), "r"(a[2]), "r"(a[3]), "r"(b[0]), "r"(b[1]));
}

// warp-level wait until chunk counter reaches target (producers use release-atomic)
__device__ __forceinline__ void chunk_wait(int ch, int target, int lane){
    if (lane == 0){
        const volatile int* c = &g_chcnt[ch];
        while (*c < target) __nanosleep(64);
    }
    __syncwarp();
}

// ---------------- conversion pre-kernels ----------------
__global__ void cvt_inputs(const float* __restrict__ in){
    size_t i = (size_t)(blockIdx.x * blockDim.x + threadIdx.x) * 8;
    if (i < (size_t)S_LEN * NBATCH * IN_DIM){
        float4 v0 = *reinterpret_cast<const float4*>(in + i);
        float4 v1 = *reinterpret_cast<const float4*>(in + i + 4);
        __half2* d = reinterpret_cast<__half2*>(&g_xh[i]);
        d[0] = __floats2half2_rn(v0.x, v0.y);
        d[1] = __floats2half2_rn(v0.z, v0.w);
        d[2] = __floats2half2_rn(v1.x, v1.y);
        d[3] = __floats2half2_rn(v1.z, v1.w);
    }
}
__global__ void cvt_wih(const float* __restrict__ W_ih,
                        const float* __restrict__ b_ih, const float* __restrict__ b_hh,
                        const float* __restrict__ h0){
    int idx = blockIdx.x * blockDim.x + threadIdx.x;
    if (idx < GDIM * (IN_DIM / 4)){
        int g = idx >> 7;
        int c = (idx & 127) * 4;
        int r = (g & 3) * HID + (g >> 2);
        float4 v = *reinterpret_cast<const float4*>(W_ih + (size_t)r * IN_DIM + c);
        __half2* d = reinterpret_cast<__half2*>(&g_wih[(size_t)g * IN_DIM + c]);
        d[0] = __floats2half2_rn(v.x, v.y);
        d[1] = __floats2half2_rn(v.z, v.w);
        if (c == 0) g_bias[g] = b_ih[r] + b_hh[r];
    }
    if (idx < NBATCH * HID) g_hh[0][idx] = __float2half_rn(h0[idx]);
    if (idx < NCH) g_chcnt[idx] = 0;
}

// ---------------- phase 1: x_proj, 128x128 tiles, cp.async pipeline ----------------
__global__ __launch_bounds__(NTHREADS)
void xproj_gemm()
{
    __shared__ __half sa[2][BM * KPAD];
    __shared__ __half sb[2][BN * KPAD];
    const int tid = threadIdx.x, lane = tid & 31, wid = tid >> 5;
    const int warp_m = wid & 3;     // 0..3 : 32 rows
    const int warp_n = wid >> 2;    // 0..1 : 64 cols
    const int m0 = blockIdx.y * BM, n0 = blockIdx.x * BN;

    float acc[2][4][2][4];   // [mt][nb][nt][4]
    #pragma unroll
    for (int a = 0; a < 2; a++)
        #pragma unroll
        for (int b = 0; b < 4; b++)
            #pragma unroll
            for (int c = 0; c < 2; c++)
                #pragma unroll
                for (int d = 0; d < 4; d++) acc[a][b][c][d] = 0.0f;

    // load mapping: 1024 16B-chunks per stage (A 512 + B 512), 4 per thread
    int pr[4], pc[4], pp_[4];
    const __half* gsrc[4];
    #pragma unroll
    for (int i = 0; i < 4; i++){
        int idx = tid + i * NTHREADS;
        pp_[i] = idx >> 9;               // 0=A, 1=B
        int w = idx & 511;
        pr[i] = w >> 2;                  // row 0..127
        pc[i] = w & 3;                   // 16B chunk 0..3
        gsrc[i] = pp_[i] ? (g_wih + (size_t)(n0 + pr[i]) * IN_DIM + pc[i] * 8)
                         : (g_xh  + (size_t)(m0 + pr[i]) * IN_DIM + pc[i] * 8);
    }

    const int KITERS = IN_DIM / BKK;   // 16
    // prologue: stage 0
    #pragma unroll
    for (int i = 0; i < 4; i++){
        __half* base = pp_[i] ? sb[0] : sa[0];
        cpasync16(su32(base + pr[i] * KPAD + pc[i] * 8), gsrc[i]);
    }
    CP_COMMIT();

    for (int kt = 0; kt < KITERS; kt++){
        if (kt + 1 < KITERS){
            int st = (kt + 1) & 1;
            #pragma unroll
            for (int i = 0; i < 4; i++){
                __half* base = pp_[i] ? sb[st] : sa[st];
                cpasync16(su32(base + pr[i] * KPAD + pc[i] * 8), gsrc[i] + (kt + 1) * BKK);
            }
            CP_COMMIT();
            CP_WAIT(1);
        } else {
            CP_WAIT(0);
        }
        __syncthreads();

        const __half* at = sa[kt & 1];
        const __half* bt = sb[kt & 1];
        #pragma unroll
        for (int kk = 0; kk < 2; kk++){
            const int lrow = lane & 15;
            const int lcol = kk * 16 + ((lane >> 4) << 3);
            unsigned ah[2][4];
            #pragma unroll
            for (int mt = 0; mt < 2; mt++){
                int r = warp_m * 32 + mt * 16 + lrow;
                ldmx4(ah[mt], su32(&at[r * KPAD + lcol]));
            }
            #pragma unroll
            for (int nb = 0; nb < 4; nb++){
                unsigned b[2][2];
                int r = warp_n * 64 + nb * 16 + lrow;
                unsigned t4[4];
                ldmx4(t4, su32(&bt[r * KPAD + lcol]));
                b[0][0] = t4[0]; b[1][0] = t4[1]; b[0][1] = t4[2]; b[1][1] = t4[3];
                #pragma unroll
                for (int mt = 0; mt < 2; mt++)
                    #pragma unroll
                    for (int nt = 0; nt < 2; nt++)
                        mma_f16(acc[mt][nb][nt], ah[mt], b[nt]);
            }
        }
        __syncthreads();
    }

    #pragma unroll
    for (int mt = 0; mt < 2; mt++)
        #pragma unroll
        for (int nb = 0; nb < 4; nb++)
            #pragma unroll
            for (int nt = 0; nt < 2; nt++)
                #pragma unroll
                for (int pp = 0; pp < 2; pp++){
                    int row = m0 + warp_m * 32 + mt * 16 + (lane >> 2) + 8 * pp;
                    int col = n0 + warp_n * 64 + nb * 16 + nt * 8 + 2 * (lane & 3);
                    float* dst = &g_xp[(size_t)row * GDIM + col];
                    dst[0] = acc[mt][nb][nt][2 * pp]     + g_bias[col];
                    dst[1] = acc[mt][nb][nt][2 * pp + 1] + g_bias[col + 1];
                }
}

// ---------------- persistent recurrence (flag-synced, fp16, 128 CTAs) ----------------
__device__ __forceinline__ void load_chunk(unsigned abase_st, const __half* hsrc,
                                           int m0, int kt, int tid){
    #pragma unroll
    for (int i = 0; i < 4; i++){
        int u = tid + i * PTH;
        int r = u >> 5;
        int c16 = u & 31;
        const __half* src = hsrc + (size_t)(m0 + r) * HID + kt * 256 + c16 * 8;
        unsigned dst = abase_st + r * 512 + ((((c16 ^ r) & 7) | (c16 & 24)) << 4);
        cpasync16(dst, src);
    }
}

__global__ __launch_bounds__(PTH, 1)
void lstm_rec(const float* __restrict__ W_hh, const float* __restrict__ c0)
{
    extern __shared__ __align__(1024) char dyn[];
    const int tid  = threadIdx.x;
    const int lane = tid & 31;
    const int wid  = tid >> 5;
    const int warp_m = wid >> 2;
    const int warp_n = wid & 3;
    const int m0 = (blockIdx.x & 1) * 64;
    const int n0 = (blockIdx.x >> 1) * 64;
    const int mychunk = blockIdx.x >> 5;   // chunk this CTA's h-units belong to
    const unsigned wbase = su32(dyn + OFF_W);
    const unsigned abase = su32(dyn + OFF_A);

    // one-time: gather + convert W_hh slice -> fp16, XOR-swizzled 2048B rows
    for (int idx = tid; idx < 64 * (HID / 8); idx += PTH){
        int j  = idx >> 7;
        int c8 = idx & 127;
        int c  = c8 * 8;
        int g  = n0 + j;
        const float* src = W_hh + (size_t)((g & 3) * HID + (g >> 2)) * HID + c;
        float4 v0 = *reinterpret_cast<const float4*>(src);
        float4 v1 = *reinterpret_cast<const float4*>(src + 4);
        int sc = (c8 & ~7) | ((c8 ^ j) & 7);
        __half2* d = reinterpret_cast<__half2*>(dyn + OFF_W + j * 2048 + (sc << 4));
        d[0] = __floats2half2_rn(v0.x, v0.y);
        d[1] = __floats2half2_rn(v0.z, v0.w);
        d[2] = __floats2half2_rn(v1.x, v1.y);
        d[3] = __floats2half2_rn(v1.z, v1.w);
    }

    const int erow = tid >> 3;
    const int q    = tid & 7;
    const int grow = m0 + erow;
    const int ub   = (n0 >> 2) + q * 2;
    float creg0 = c0[grow * HID + ub];
    float creg1 = c0[grow * HID + ub + 1];
    __syncthreads();

    for (int s = 0; s < S_LEN; s++){
        const __half* hsrc = g_hh[s & 1];
        const int target = 32 * s;

        const float* xpr = g_xp + ((size_t)s * NBATCH + grow) * GDIM + n0 + q * 8;
        float4 xv0 = *reinterpret_cast<const float4*>(xpr);
        float4 xv1 = *reinterpret_cast<const float4*>(xpr + 4);

        float acc[2][4];
        #pragma unroll
        for (int j = 0; j < 2; j++)
            #pragma unroll
            for (int k = 0; k < 4; k++) acc[j][k] = 0.0f;

        chunk_wait(0, target, lane);
        load_chunk(abase + 0 * CHB, hsrc, m0, 0, tid); CP_COMMIT();
        chunk_wait(1, target, lane);
        load_chunk(abase + 1 * CHB, hsrc, m0, 1, tid); CP_COMMIT();

        for (int kt = 0; kt < NCH; kt++){
            if (kt + 2 < NCH){
                chunk_wait(kt + 2, target, lane);
                load_chunk(abase + ((kt + 2) % 3) * CHB, hsrc, m0, kt + 2, tid);
                CP_COMMIT();
                CP_WAIT(2);
            } else if (kt == NCH - 2){
                CP_WAIT(1);
            } else {
                CP_WAIT(0);
            }
            __syncthreads();

            const unsigned ab = abase + (kt % 3) * CHB;
            #pragma unroll
            for (int kkl = 0; kkl < 16; kkl++){
                const int lrow = lane & 15;
                const int koff = kkl * 16 + ((lane >> 4) << 3);
                const int c16  = koff >> 3;
                unsigned ah[4];
                {
                    int r = warp_m * 16 + lrow;
                    ldmx4(ah, ab + r * 512 + ((((c16 ^ r) & 7) | (c16 & 24)) << 4));
                }
                unsigned b[2][2];
                {
                    int r = warp_n * 16 + lrow;
                    int c8 = (kt * 256 + koff) >> 3;
                    unsigned t4[4];
                    ldmx4(t4, wbase + r * 2048 + (((c8 & ~7) | ((c8 ^ r) & 7)) << 4));
                    b[0][0] = t4[0]; b[1][0] = t4[1]; b[0][1] = t4[2]; b[1][1] = t4[3];
                }
                #pragma unroll
                for (int nt = 0; nt < 2; nt++)
                    mma_f16(acc[nt], ah, b[nt]);
            }
            __syncthreads();
        }

        // stage gates (16KB in stage-0 buffer)
        float* gates = (float*)(dyn + OFF_A);
        #pragma unroll
        for (int nt = 0; nt < 2; nt++)
            #pragma unroll
            for (int pp = 0; pp < 2; pp++){
                int row = warp_m * 16 + (lane >> 2) + 8 * pp;
                int col = warp_n * 16 + nt * 8 + 2 * (lane & 3);
                gates[row * 64 + col]     = acc[nt][2 * pp];
                gates[row * 64 + col + 1] = acc[nt][2 * pp + 1];
            }
        __syncthreads();

        {
            const float* gr = &gates[erow * 64 + q * 8];
            float4 g0 = *reinterpret_cast<const float4*>(gr);
            float4 g1 = *reinterpret_cast<const float4*>(gr + 4);

            float ig = sigmoidf_(g0.x + xv0.x);
            float fg = sigmoidf_(g0.y + xv0.y);
            float gg = tanhf    (g0.z + xv0.z);
            float og = sigmoidf_(g0.w + xv0.w);
            creg0 = fg * creg0 + ig * gg;
            float hv0 = og * tanhf(creg0);

            ig = sigmoidf_(g1.x + xv1.x);
            fg = sigmoidf_(g1.y + xv1.y);
            gg = tanhf    (g1.z + xv1.z);
            og = sigmoidf_(g1.w + xv1.w);
            creg1 = fg * creg1 + ig * gg;
            float hv1 = og * tanhf(creg1);

            *reinterpret_cast<__half2*>(&g_hh[(s + 1) & 1][grow * HID + ub]) =
                __halves2half2(__float2half_rn(hv0), __float2half_rn(hv1));
        }

        __syncthreads();      // all h writes + gates reads done
        if (tid == 0){
            __threadfence();  // publish h before flag
            atomicAdd(&g_chcnt[mychunk], 1);
        }
    }
}

// ---------------- decode (1024 threads, 8-way K split) ----------------
__global__ void lstm_decode(const float* __restrict__ W_dec, const float* __restrict__ b_dec,
                            float* __restrict__ out){
    __shared__ float wsh[NOUT * HID];
    __shared__ float lsh[NOUT * NBATCH];
    __shared__ float red[2 * NOUT];
    int tid = threadIdx.x;
    for (int i = tid; i < NOUT * HID; i += 1024) wsh[i] = W_dec[i];
    __syncthreads();
    int b = tid >> 3, kseg = tid & 7;
    const uint4* hp = reinterpret_cast<const uint4*>(&g_hh[0][b * HID + kseg * 128]);
    float a[4] = {0.f, 0.f, 0.f, 0.f};
    #pragma unroll 4
    for (int v = 0; v < 16; v++){
        uint4 pk = hp[v];
        const __half* h8 = reinterpret_cast<const __half*>(&pk);
        #pragma unroll
        for (int e = 0; e < 8; e++){
            float hv = __half2float(h8[e]);
            int kk = kseg * 128 + v * 8 + e;
            a[0] += hv * wsh[kk];
            a[1] += hv * wsh[HID + kk];
            a[2] += hv * wsh[2 * HID + kk];
            a[3] += hv * wsh[3 * HID + kk];
        }
    }
    #pragma unroll
    for (int o = 0; o < 4; o++){
        a[o] += __shfl_xor_sync(0xFFFFFFFFu, a[o], 1);
        a[o] += __shfl_xor_sync(0xFFFFFFFFu, a[o], 2);
        a[o] += __shfl_xor_sync(0xFFFFFFFFu, a[o], 4);
    }
    if (kseg == 0){
        #pragma unroll
        for (int o = 0; o < 4; o++) lsh[o * NBATCH + b] = a[o] + b_dec[o];
    }
    __syncthreads();
    if (tid < NOUT){
        int o = tid;
        float m = -1e30f;
        for (int j = 0; j < NBATCH; j++) m = fmaxf(m, lsh[o * NBATCH + j]);
        float sum = 0.0f;
        for (int j = 0; j < NBATCH; j++) sum += expf(lsh[o * NBATCH + j] - m);
        red[o] = m; red[NOUT + o] = sum;
    }
    __syncthreads();
    if (tid < NBATCH){
        #pragma unroll
        for (int o = 0; o < NOUT; o++)
            out[tid * NOUT + o] = expf(lsh[o * NBATCH + tid] - red[o]) / red[NOUT + o];
    }
}

// ---------------- launch ----------------
extern "C" void kernel_launch(void* const* d_in, const int* in_sizes, int n_in,
                              void* d_out, int out_size)
{
    const float* inputs = (const float*)d_in[0];
    const float* h0     = (const float*)d_in[1];
    const float* c0     = (const float*)d_in[2];
    const float* W_ih   = (const float*)d_in[3];
    const float* W_hh   = (const float*)d_in[4];
    const float* b_ih   = (const float*)d_in[5];
    const float* b_hh   = (const float*)d_in[6];
    const float* W_dec  = (const float*)d_in[7];
    const float* b_dec  = (const float*)d_in[8];
    float* out = (float*)d_out;

    cudaFuncSetAttribute(lstm_rec, cudaFuncAttributeMaxDynamicSharedMemorySize, DYN_B);

    {
        int n8 = (S_LEN * NBATCH * IN_DIM) / 8;
        cvt_inputs<<<(n8 + 255) / 256, 256>>>(inputs);
        int nw = GDIM * (IN_DIM / 4);
        cvt_wih<<<(nw + 255) / 256, 256>>>(W_ih, b_ih, b_hh, h0);
    }

    dim3 g1(GDIM / BN, (S_LEN * NBATCH) / BM);   // 32 x 512
    xproj_gemm<<<g1, NTHREADS>>>();

    lstm_rec<<<PGRID, PTH, DYN_B>>>(W_hh, c0);

    lstm_decode<<<1, 1024>>>(W_dec, b_dec, out);
}

// round 9
// speedup vs baseline: 1.0339x; 1.0339x over previous
#include <cuda_runtime.h>
#include <cuda_bf16.h>
#include <cuda_fp16.h>
#include <math.h>
#include <stdint.h>

#define S_LEN   512
#define NBATCH  128
#define IN_DIM  512
#define HID     1024
#define GDIM    4096   // interleaved: col g -> gate g&3, unit g>>2
#define NOUT    4

// phase-1 tiling (R7-proven 64x64)
#define BM 64
#define BN 64
#define BKK 32
#define KPAD 40
#define NTHREADS 256

// recurrence: 128 CTAs = 2 row-halves x 64 col-tiles, each 64x64xK
#define PGRID 128
#define PTH 512
#define NCH 4                    // K chunks of 256
#define CHB 32768                // chunk: 64 rows x 512B
#define WB  131072               // W: 64 gate-cols x 2048B
#define OFF_W 0
#define OFF_A WB
#define DYN_B (WB + 3 * CHB)     // 229376

__device__ float  g_xp[(size_t)S_LEN * NBATCH * GDIM];
__device__ __half g_xh[(size_t)S_LEN * NBATCH * IN_DIM];
__device__ __half g_wih[(size_t)GDIM * IN_DIM];
__device__ float  g_bias[GDIM];
__device__ __half g_hh[2][NBATCH * HID];
__device__ int g_bar_count[2];
__device__ volatile int g_bar_phase[2];

__device__ __forceinline__ unsigned su32(const void* p){
    return (unsigned)__cvta_generic_to_shared(p);
}
__device__ __forceinline__ float sigmoidf_(float x){ return 1.0f / (1.0f + expf(-x)); }
__device__ __forceinline__ void cpasync16(unsigned saddr, const void* g){
    asm volatile("cp.async.cg.shared.global [%0], [%1], 16;" :: "r"(saddr), "l"(g));
}
#define CP_COMMIT() asm volatile("cp.async.commit_group;")
#define CP_WAIT(n)  asm volatile("cp.async.wait_group %0;" :: "n"(n))

__device__ __forceinline__ void ldmx4(unsigned* r, unsigned addr){
    asm volatile("ldmatrix.sync.aligned.m8n8.x4.shared.b16 {%0,%1,%2,%3}, [%4];"
        : "=r"(r[0]), "=r"(r[1]), "=r"(r[2]), "=r"(r[3]) : "r"(addr));
}
__device__ __forceinline__ void mma_f16(float* d, const unsigned* a, const unsigned* b){
    asm volatile("mma.sync.aligned.m16n8k16.row.col.f32.f16.f16.f32 "
        "{%0,%1,%2,%3},{%4,%5,%6,%7},{%8,%9},{%0,%1,%2,%3};"
        : "+f"(d[0]), "+f"(d[1]), "+f"(d[2]), "+f"(d[3])
        : "r"(a[0]), "r"(a[1]), "r"(a[2]), "r"(a[3]), "r"(b[0]), "r"(b[1]));
}

// per-row-half barrier: only 64 CTAs participate in each
__device__ __forceinline__ void half_barrier(int half, int* sense){
    __threadfence();
    __syncthreads();
    if (threadIdx.x == 0){
        int target = *sense ^ 1;
        if (atomicAdd(&g_bar_count[half], 1) == 63){
            atomicExch(&g_bar_count[half], 0);
            __threadfence();
            g_bar_phase[half] = target;
        } else {
            while (g_bar_phase[half] != target) __nanosleep(32);
        }
        *sense = target;
    }
    __syncthreads();
    __threadfence();
}

// ---------------- conversion pre-kernels ----------------
__global__ void cvt_inputs(const float* __restrict__ in){
    size_t i = (size_t)(blockIdx.x * blockDim.x + threadIdx.x) * 8;
    if (i < (size_t)S_LEN * NBATCH * IN_DIM){
        float4 v0 = *reinterpret_cast<const float4*>(in + i);
        float4 v1 = *reinterpret_cast<const float4*>(in + i + 4);
        __half2* d = reinterpret_cast<__half2*>(&g_xh[i]);
        d[0] = __floats2half2_rn(v0.x, v0.y);
        d[1] = __floats2half2_rn(v0.z, v0.w);
        d[2] = __floats2half2_rn(v1.x, v1.y);
        d[3] = __floats2half2_rn(v1.z, v1.w);
    }
}
__global__ void cvt_wih(const float* __restrict__ W_ih,
                        const float* __restrict__ b_ih, const float* __restrict__ b_hh,
                        const float* __restrict__ h0){
    int idx = blockIdx.x * blockDim.x + threadIdx.x;
    if (idx < GDIM * (IN_DIM / 4)){
        int g = idx >> 7;
        int c = (idx & 127) * 4;
        int r = (g & 3) * HID + (g >> 2);
        float4 v = *reinterpret_cast<const float4*>(W_ih + (size_t)r * IN_DIM + c);
        __half2* d = reinterpret_cast<__half2*>(&g_wih[(size_t)g * IN_DIM + c]);
        d[0] = __floats2half2_rn(v.x, v.y);
        d[1] = __floats2half2_rn(v.z, v.w);
        if (c == 0) g_bias[g] = b_ih[r] + b_hh[r];
    }
    if (idx < NBATCH * HID) g_hh[0][idx] = __float2half_rn(h0[idx]);
    if (idx < 2){ g_bar_count[idx] = 0; g_bar_phase[idx] = 0; }
}

// ---------------- phase 1: x_proj (R7-proven, single-pass fp16) ----------------
struct P1Smem {
    __half a[BM * KPAD];
    __half b[BN * KPAD];
};

__global__ __launch_bounds__(NTHREADS)
void xproj_gemm()
{
    __shared__ P1Smem sm;
    const int tid = threadIdx.x, lane = tid & 31, wid = tid >> 5;
    const int warp_m = wid >> 2, warp_n = wid & 3;
    const int m0 = blockIdx.y * BM, n0 = blockIdx.x * BN;

    float acc[2][2][4];
    #pragma unroll
    for (int i = 0; i < 2; i++)
        #pragma unroll
        for (int j = 0; j < 2; j++)
            #pragma unroll
            for (int k = 0; k < 4; k++) acc[i][j][k] = 0.0f;

    const int lrw = tid >> 2;
    const int lcc = (tid & 3) * 8;
    const __half* asrc = g_xh  + (size_t)(m0 + lrw) * IN_DIM + lcc;
    const __half* bsrc = g_wih + (size_t)(n0 + lrw) * IN_DIM + lcc;

    uint4 pa = *reinterpret_cast<const uint4*>(asrc);
    uint4 pb = *reinterpret_cast<const uint4*>(bsrc);

    const int KITERS = IN_DIM / BKK;
    for (int kt = 0; kt < KITERS; kt++){
        *reinterpret_cast<uint4*>(&sm.a[lrw * KPAD + lcc]) = pa;
        *reinterpret_cast<uint4*>(&sm.b[lrw * KPAD + lcc]) = pb;
        __syncthreads();
        if (kt + 1 < KITERS){
            pa = *reinterpret_cast<const uint4*>(asrc + (kt + 1) * BKK);
            pb = *reinterpret_cast<const uint4*>(bsrc + (kt + 1) * BKK);
        }
        #pragma unroll
        for (int kk = 0; kk < 2; kk++){
            const int lrow = lane & 15;
            const int lcol = kk * 16 + ((lane >> 4) << 3);
            unsigned ah[2][4];
            #pragma unroll
            for (int mt = 0; mt < 2; mt++){
                int r = warp_m * 32 + mt * 16 + lrow;
                ldmx4(ah[mt], su32(&sm.a[r * KPAD + lcol]));
            }
            unsigned b[2][2];
            {
                int r = warp_n * 16 + lrow;
                unsigned t4[4];
                ldmx4(t4, su32(&sm.b[r * KPAD + lcol]));
                b[0][0] = t4[0]; b[1][0] = t4[1]; b[0][1] = t4[2]; b[1][1] = t4[3];
            }
            #pragma unroll
            for (int mt = 0; mt < 2; mt++)
                #pragma unroll
                for (int nt = 0; nt < 2; nt++)
                    mma_f16(acc[mt][nt], ah[mt], b[nt]);
        }
        __syncthreads();
    }

    #pragma unroll
    for (int mt = 0; mt < 2; mt++)
        #pragma unroll
        for (int nt = 0; nt < 2; nt++)
            #pragma unroll
            for (int pp = 0; pp < 2; pp++){
                int row = m0 + warp_m * 32 + mt * 16 + (lane >> 2) + 8 * pp;
                int col = n0 + warp_n * 16 + nt * 8 + 2 * (lane & 3);
                float* dst = &g_xp[(size_t)row * GDIM + col];
                dst[0] = acc[mt][nt][2 * pp]     + g_bias[col];
                dst[1] = acc[mt][nt][2 * pp + 1] + g_bias[col + 1];
            }
}

// ---------------- persistent recurrence (M-split, shuffle epilogue) ----------------
__device__ __forceinline__ void load_chunk(unsigned abase_st, const __half* hsrc,
                                           int m0, int kt, int tid){
    #pragma unroll
    for (int i = 0; i < 4; i++){
        int u = tid + i * PTH;
        int r = u >> 5;
        int c16 = u & 31;
        const __half* src = hsrc + (size_t)(m0 + r) * HID + kt * 256 + c16 * 8;
        unsigned dst = abase_st + r * 512 + ((((c16 ^ r) & 7) | (c16 & 24)) << 4);
        cpasync16(dst, src);
    }
}

__global__ __launch_bounds__(PTH, 1)
void lstm_rec(const float* __restrict__ W_hh, const float* __restrict__ c0)
{
    extern __shared__ __align__(1024) char dyn[];
    const int tid  = threadIdx.x;
    const int lane = tid & 31;
    const int wid  = tid >> 5;
    const int warp_m = wid >> 2;    // 0..3 : 16 rows each
    const int warp_n = wid & 3;     // 0..3 : 16 cols each
    const int half = blockIdx.x & 1;
    const int m0 = half * 64;
    const int n0 = (blockIdx.x >> 1) * 64;
    const unsigned wbase = su32(dyn + OFF_W);
    const unsigned abase = su32(dyn + OFF_A);

    // one-time: gather + convert W_hh slice -> fp16, XOR-swizzled 2048B rows
    for (int idx = tid; idx < 64 * (HID / 8); idx += PTH){
        int j  = idx >> 7;
        int c8 = idx & 127;
        int c  = c8 * 8;
        int g  = n0 + j;
        const float* src = W_hh + (size_t)((g & 3) * HID + (g >> 2)) * HID + c;
        float4 v0 = *reinterpret_cast<const float4*>(src);
        float4 v1 = *reinterpret_cast<const float4*>(src + 4);
        int sc = (c8 & ~7) | ((c8 ^ j) & 7);
        __half2* d = reinterpret_cast<__half2*>(dyn + OFF_W + j * 2048 + (sc << 4));
        d[0] = __floats2half2_rn(v0.x, v0.y);
        d[1] = __floats2half2_rn(v0.z, v0.w);
        d[2] = __floats2half2_rn(v1.x, v1.y);
        d[3] = __floats2half2_rn(v1.z, v1.w);
    }

    // epilogue ownership (mma fragment layout): lane pair (lane, lane^1)
    // covers unit (lane&3)>>1, rows r and r+8; even lane -> row r, odd -> row r+8
    const int evenl = (lane & 1) == 0;
    const int myrow = m0 + warp_m * 16 + (lane >> 2) + (evenl ? 0 : 8);
    int myunit[2];
    #pragma unroll
    for (int nt = 0; nt < 2; nt++)
        myunit[nt] = (n0 + warp_n * 16 + nt * 8 + ((lane & 3) >> 1) * 4) >> 2;

    float creg[2];
    #pragma unroll
    for (int nt = 0; nt < 2; nt++) creg[nt] = c0[myrow * HID + myunit[nt]];
    __syncthreads();

    int sense = 0;
    for (int s = 0; s < S_LEN; s++){
        const __half* hsrc = g_hh[s & 1];

        // prefetch x_proj gate quads for epilogue
        float4 xv[2];
        #pragma unroll
        for (int nt = 0; nt < 2; nt++)
            xv[nt] = *reinterpret_cast<const float4*>(
                g_xp + ((size_t)s * NBATCH + myrow) * GDIM + myunit[nt] * 4);

        float acc[2][4];
        #pragma unroll
        for (int j = 0; j < 2; j++)
            #pragma unroll
            for (int k = 0; k < 4; k++) acc[j][k] = 0.0f;

        load_chunk(abase + 0 * CHB, hsrc, m0, 0, tid); CP_COMMIT();
        load_chunk(abase + 1 * CHB, hsrc, m0, 1, tid); CP_COMMIT();

        for (int kt = 0; kt < NCH; kt++){
            if (kt + 2 < NCH){
                load_chunk(abase + ((kt + 2) % 3) * CHB, hsrc, m0, kt + 2, tid);
                CP_COMMIT();
                CP_WAIT(2);
            } else if (kt == NCH - 2){
                CP_WAIT(1);
            } else {
                CP_WAIT(0);
            }
            __syncthreads();

            const unsigned ab = abase + (kt % 3) * CHB;
            #pragma unroll
            for (int kkl = 0; kkl < 16; kkl++){
                const int lrow = lane & 15;
                const int koff = kkl * 16 + ((lane >> 4) << 3);
                const int c16  = koff >> 3;
                unsigned ah[4];
                {
                    int r = warp_m * 16 + lrow;
                    ldmx4(ah, ab + r * 512 + ((((c16 ^ r) & 7) | (c16 & 24)) << 4));
                }
                unsigned b[2][2];
                {
                    int r = warp_n * 16 + lrow;
                    int c8 = (kt * 256 + koff) >> 3;
                    unsigned t4[4];
                    ldmx4(t4, wbase + r * 2048 + (((c8 & ~7) | ((c8 ^ r) & 7)) << 4));
                    b[0][0] = t4[0]; b[1][0] = t4[1]; b[0][1] = t4[2]; b[1][1] = t4[3];
                }
                #pragma unroll
                for (int nt = 0; nt < 2; nt++)
                    mma_f16(acc[nt], ah, b[nt]);
            }
            __syncthreads();
        }

        // shuffle epilogue: assemble i,f,g,o in-register (no smem staging)
        __half* hdst = g_hh[(s + 1) & 1];
        #pragma unroll
        for (int nt = 0; nt < 2; nt++){
            float plox = __shfl_xor_sync(0xFFFFFFFFu, acc[nt][0], 1);
            float ploy = __shfl_xor_sync(0xFFFFFFFFu, acc[nt][1], 1);
            float phix = __shfl_xor_sync(0xFFFFFFFFu, acc[nt][2], 1);
            float phiy = __shfl_xor_sync(0xFFFFFFFFu, acc[nt][3], 1);
            float gi, gf, gg, go;
            if (evenl){ gi = acc[nt][0]; gf = acc[nt][1]; gg = plox; go = ploy; }
            else      { gi = phix;       gf = phiy;       gg = acc[nt][2]; go = acc[nt][3]; }
            float ig = sigmoidf_(gi + xv[nt].x);
            float fg = sigmoidf_(gf + xv[nt].y);
            float g2 = tanhf    (gg + xv[nt].z);
            float og = sigmoidf_(go + xv[nt].w);
            creg[nt] = fg * creg[nt] + ig * g2;
            hdst[myrow * HID + myunit[nt]] = __float2half_rn(og * tanhf(creg[nt]));
        }

        half_barrier(half, &sense);
    }
}

// ---------------- decode (1024 threads, 8-way K split) ----------------
__global__ void lstm_decode(const float* __restrict__ W_dec, const float* __restrict__ b_dec,
                            float* __restrict__ out){
    __shared__ float wsh[NOUT * HID];
    __shared__ float lsh[NOUT * NBATCH];
    __shared__ float red[2 * NOUT];
    int tid = threadIdx.x;
    for (int i = tid; i < NOUT * HID; i += 1024) wsh[i] = W_dec[i];
    __syncthreads();
    int b = tid >> 3, kseg = tid & 7;
    const uint4* hp = reinterpret_cast<const uint4*>(&g_hh[0][b * HID + kseg * 128]);
    float a[4] = {0.f, 0.f, 0.f, 0.f};
    #pragma unroll 4
    for (int v = 0; v < 16; v++){
        uint4 pk = hp[v];
        const __half* h8 = reinterpret_cast<const __half*>(&pk);
        #pragma unroll
        for (int e = 0; e < 8; e++){
            float hv = __half2float(h8[e]);
            int kk = kseg * 128 + v * 8 + e;
            a[0] += hv * wsh[kk];
            a[1] += hv * wsh[HID + kk];
            a[2] += hv * wsh[2 * HID + kk];
            a[3] += hv * wsh[3 * HID + kk];
        }
    }
    #pragma unroll
    for (int o = 0; o < 4; o++){
        a[o] += __shfl_xor_sync(0xFFFFFFFFu, a[o], 1);
        a[o] += __shfl_xor_sync(0xFFFFFFFFu, a[o], 2);
        a[o] += __shfl_xor_sync(0xFFFFFFFFu, a[o], 4);
    }
    if (kseg == 0){
        #pragma unroll
        for (int o = 0; o < 4; o++) lsh[o * NBATCH + b] = a[o] + b_dec[o];
    }
    __syncthreads();
    if (tid < NOUT){
        int o = tid;
        float m = -1e30f;
        for (int j = 0; j < NBATCH; j++) m = fmaxf(m, lsh[o * NBATCH + j]);
        float sum = 0.0f;
        for (int j = 0; j < NBATCH; j++) sum += expf(lsh[o * NBATCH + j] - m);
        red[o] = m; red[NOUT + o] = sum;
    }
    __syncthreads();
    if (tid < NBATCH){
        #pragma unroll
        for (int o = 0; o < NOUT; o++)
            out[tid * NOUT + o] = expf(lsh[o * NBATCH + tid] - red[o]) / red[NOUT + o];
    }
}

// ---------------- launch ----------------
extern "C" void kernel_launch(void* const* d_in, const int* in_sizes, int n_in,
                              void* d_out, int out_size)
{
    const float* inputs = (const float*)d_in[0];
    const float* h0     = (const float*)d_in[1];
    const float* c0     = (const float*)d_in[2];
    const float* W_ih   = (const float*)d_in[3];
    const float* W_hh   = (const float*)d_in[4];
    const float* b_ih   = (const float*)d_in[5];
    const float* b_hh   = (const float*)d_in[6];
    const float* W_dec  = (const float*)d_in[7];
    const float* b_dec  = (const float*)d_in[8];
    float* out = (float*)d_out;

    cudaFuncSetAttribute(lstm_rec, cudaFuncAttributeMaxDynamicSharedMemorySize, DYN_B);

    {
        int n8 = (S_LEN * NBATCH * IN_DIM) / 8;
        cvt_inputs<<<(n8 + 255) / 256, 256>>>(inputs);
        int nw = GDIM * (IN_DIM / 4);
        cvt_wih<<<(nw + 255) / 256, 256>>>(W_ih, b_ih, b_hh, h0);
    }

    dim3 g1(GDIM / BN, (S_LEN * NBATCH) / BM);
    xproj_gemm<<<g1, NTHREADS>>>();

    lstm_rec<<<PGRID, PTH, DYN_B>>>(W_hh, c0);

    lstm_decode<<<1, 1024>>>(W_dec, b_dec, out);
}

// round 10
// speedup vs baseline: 1.0378x; 1.0038x over previous
#include <cuda_runtime.h>
#include <cuda_bf16.h>
#include <cuda_fp16.h>
#include <math.h>
#include <stdint.h>

#define S_LEN   512
#define NBATCH  128
#define IN_DIM  512
#define HID     1024
#define GDIM    4096   // interleaved: col g -> gate g&3, unit g>>2
#define NOUT    4

// phase-1 tiling (R7-proven 64x64)
#define BM 64
#define BN 64
#define BKK 32
#define KPAD 40
#define NTHREADS 256

// recurrence: 128 CTAs = 2 row-halves x 64 col-tiles, each 64x64xK
#define PGRID 128
#define PTH 512
#define NCH 4                    // K chunks of 256
#define CHB 32768                // chunk: 64 rows x 512B
#define WB  131072               // W: 64 gate-cols x 2048B
#define OFF_W 0
#define OFF_A WB
#define DYN_B (WB + 3 * CHB)     // 229376

__device__ float  g_xp[(size_t)S_LEN * NBATCH * GDIM];
__device__ __half g_xh[(size_t)S_LEN * NBATCH * IN_DIM];
__device__ __half g_wih[(size_t)GDIM * IN_DIM];
__device__ float  g_bias[GDIM];
__device__ __half g_hh[2][NBATCH * HID];
__device__ int g_bar_count;
__device__ volatile int g_bar_phase;

__device__ __forceinline__ unsigned su32(const void* p){
    return (unsigned)__cvta_generic_to_shared(p);
}
__device__ __forceinline__ float sigmoidf_(float x){ return 1.0f / (1.0f + expf(-x)); }
__device__ __forceinline__ void cpasync16(unsigned saddr, const void* g){
    asm volatile("cp.async.cg.shared.global [%0], [%1], 16;" :: "r"(saddr), "l"(g));
}
#define CP_COMMIT() asm volatile("cp.async.commit_group;")
#define CP_WAIT(n)  asm volatile("cp.async.wait_group %0;" :: "n"(n))

__device__ __forceinline__ void ldmx4(unsigned* r, unsigned addr){
    asm volatile("ldmatrix.sync.aligned.m8n8.x4.shared.b16 {%0,%1,%2,%3}, [%4];"
        : "=r"(r[0]), "=r"(r[1]), "=r"(r[2]), "=r"(r[3]) : "r"(addr));
}
__device__ __forceinline__ void mma_f16(float* d, const unsigned* a, const unsigned* b){
    asm volatile("mma.sync.aligned.m16n8k16.row.col.f32.f16.f16.f32 "
        "{%0,%1,%2,%3},{%4,%5,%6,%7},{%8,%9},{%0,%1,%2,%3};"
        : "+f"(d[0]), "+f"(d[1]), "+f"(d[2]), "+f"(d[3])
        : "r"(a[0]), "r"(a[1]), "r"(a[2]), "r"(a[3]), "r"(b[0]), "r"(b[1]));
}

// full grid barrier (R7-proven)
__device__ __forceinline__ void grid_barrier(int* sense){
    __threadfence();
    __syncthreads();
    if (threadIdx.x == 0){
        int target = *sense ^ 1;
        if (atomicAdd(&g_bar_count, 1) == PGRID - 1){
            atomicExch(&g_bar_count, 0);
            __threadfence();
            g_bar_phase = target;
        } else {
            while (g_bar_phase != target) __nanosleep(40);
        }
        *sense = target;
    }
    __syncthreads();
    __threadfence();
}

// ---------------- conversion pre-kernels ----------------
__global__ void cvt_inputs(const float* __restrict__ in){
    size_t i = (size_t)(blockIdx.x * blockDim.x + threadIdx.x) * 8;
    if (i < (size_t)S_LEN * NBATCH * IN_DIM){
        float4 v0 = *reinterpret_cast<const float4*>(in + i);
        float4 v1 = *reinterpret_cast<const float4*>(in + i + 4);
        __half2* d = reinterpret_cast<__half2*>(&g_xh[i]);
        d[0] = __floats2half2_rn(v0.x, v0.y);
        d[1] = __floats2half2_rn(v0.z, v0.w);
        d[2] = __floats2half2_rn(v1.x, v1.y);
        d[3] = __floats2half2_rn(v1.z, v1.w);
    }
}
__global__ void cvt_wih(const float* __restrict__ W_ih,
                        const float* __restrict__ b_ih, const float* __restrict__ b_hh,
                        const float* __restrict__ h0){
    int idx = blockIdx.x * blockDim.x + threadIdx.x;
    if (idx < GDIM * (IN_DIM / 4)){
        int g = idx >> 7;
        int c = (idx & 127) * 4;
        int r = (g & 3) * HID + (g >> 2);
        float4 v = *reinterpret_cast<const float4*>(W_ih + (size_t)r * IN_DIM + c);
        __half2* d = reinterpret_cast<__half2*>(&g_wih[(size_t)g * IN_DIM + c]);
        d[0] = __floats2half2_rn(v.x, v.y);
        d[1] = __floats2half2_rn(v.z, v.w);
        if (c == 0) g_bias[g] = b_ih[r] + b_hh[r];
    }
    if (idx < NBATCH * HID) g_hh[0][idx] = __float2half_rn(h0[idx]);
    if (idx == 0){ g_bar_count = 0; g_bar_phase = 0; }
}

// ---------------- phase 1: x_proj (R7-proven, single-pass fp16) ----------------
struct P1Smem {
    __half a[BM * KPAD];
    __half b[BN * KPAD];
};

__global__ __launch_bounds__(NTHREADS)
void xproj_gemm()
{
    __shared__ P1Smem sm;
    const int tid = threadIdx.x, lane = tid & 31, wid = tid >> 5;
    const int warp_m = wid >> 2, warp_n = wid & 3;
    const int m0 = blockIdx.y * BM, n0 = blockIdx.x * BN;

    float acc[2][2][4];
    #pragma unroll
    for (int i = 0; i < 2; i++)
        #pragma unroll
        for (int j = 0; j < 2; j++)
            #pragma unroll
            for (int k = 0; k < 4; k++) acc[i][j][k] = 0.0f;

    const int lrw = tid >> 2;
    const int lcc = (tid & 3) * 8;
    const __half* asrc = g_xh  + (size_t)(m0 + lrw) * IN_DIM + lcc;
    const __half* bsrc = g_wih + (size_t)(n0 + lrw) * IN_DIM + lcc;

    uint4 pa = *reinterpret_cast<const uint4*>(asrc);
    uint4 pb = *reinterpret_cast<const uint4*>(bsrc);

    const int KITERS = IN_DIM / BKK;
    for (int kt = 0; kt < KITERS; kt++){
        *reinterpret_cast<uint4*>(&sm.a[lrw * KPAD + lcc]) = pa;
        *reinterpret_cast<uint4*>(&sm.b[lrw * KPAD + lcc]) = pb;
        __syncthreads();
        if (kt + 1 < KITERS){
            pa = *reinterpret_cast<const uint4*>(asrc + (kt + 1) * BKK);
            pb = *reinterpret_cast<const uint4*>(bsrc + (kt + 1) * BKK);
        }
        #pragma unroll
        for (int kk = 0; kk < 2; kk++){
            const int lrow = lane & 15;
            const int lcol = kk * 16 + ((lane >> 4) << 3);
            unsigned ah[2][4];
            #pragma unroll
            for (int mt = 0; mt < 2; mt++){
                int r = warp_m * 32 + mt * 16 + lrow;
                ldmx4(ah[mt], su32(&sm.a[r * KPAD + lcol]));
            }
            unsigned b[2][2];
            {
                int r = warp_n * 16 + lrow;
                unsigned t4[4];
                ldmx4(t4, su32(&sm.b[r * KPAD + lcol]));
                b[0][0] = t4[0]; b[1][0] = t4[1]; b[0][1] = t4[2]; b[1][1] = t4[3];
            }
            #pragma unroll
            for (int mt = 0; mt < 2; mt++)
                #pragma unroll
                for (int nt = 0; nt < 2; nt++)
                    mma_f16(acc[mt][nt], ah[mt], b[nt]);
        }
        __syncthreads();
    }

    #pragma unroll
    for (int mt = 0; mt < 2; mt++)
        #pragma unroll
        for (int nt = 0; nt < 2; nt++)
            #pragma unroll
            for (int pp = 0; pp < 2; pp++){
                int row = m0 + warp_m * 32 + mt * 16 + (lane >> 2) + 8 * pp;
                int col = n0 + warp_n * 16 + nt * 8 + 2 * (lane & 3);
                float* dst = &g_xp[(size_t)row * GDIM + col];
                dst[0] = acc[mt][nt][2 * pp]     + g_bias[col];
                dst[1] = acc[mt][nt][2 * pp + 1] + g_bias[col + 1];
            }
}

// ---------------- persistent recurrence (M-split, parity-split accumulators) ----------------
__device__ __forceinline__ void load_chunk(unsigned abase_st, const __half* hsrc,
                                           int m0, int kt, int tid){
    #pragma unroll
    for (int i = 0; i < 4; i++){
        int u = tid + i * PTH;
        int r = u >> 5;
        int c16 = u & 31;
        const __half* src = hsrc + (size_t)(m0 + r) * HID + kt * 256 + c16 * 8;
        unsigned dst = abase_st + r * 512 + ((((c16 ^ r) & 7) | (c16 & 24)) << 4);
        cpasync16(dst, src);
    }
}

__global__ __launch_bounds__(PTH, 1)
void lstm_rec(const float* __restrict__ W_hh, const float* __restrict__ c0)
{
    extern __shared__ __align__(1024) char dyn[];
    const int tid  = threadIdx.x;
    const int lane = tid & 31;
    const int wid  = tid >> 5;
    const int warp_m = wid >> 2;    // 0..3 : 16 rows each
    const int warp_n = wid & 3;     // 0..3 : 16 cols each
    const int m0 = (blockIdx.x & 1) * 64;
    const int n0 = (blockIdx.x >> 1) * 64;
    const unsigned wbase = su32(dyn + OFF_W);
    const unsigned abase = su32(dyn + OFF_A);

    // one-time: gather + convert W_hh slice -> fp16, XOR-swizzled 2048B rows
    for (int idx = tid; idx < 64 * (HID / 8); idx += PTH){
        int j  = idx >> 7;
        int c8 = idx & 127;
        int c  = c8 * 8;
        int g  = n0 + j;
        const float* src = W_hh + (size_t)((g & 3) * HID + (g >> 2)) * HID + c;
        float4 v0 = *reinterpret_cast<const float4*>(src);
        float4 v1 = *reinterpret_cast<const float4*>(src + 4);
        int sc = (c8 & ~7) | ((c8 ^ j) & 7);
        __half2* d = reinterpret_cast<__half2*>(dyn + OFF_W + j * 2048 + (sc << 4));
        d[0] = __floats2half2_rn(v0.x, v0.y);
        d[1] = __floats2half2_rn(v0.z, v0.w);
        d[2] = __floats2half2_rn(v1.x, v1.y);
        d[3] = __floats2half2_rn(v1.z, v1.w);
    }

    const int erow = tid >> 3;
    const int q    = tid & 7;
    const int grow = m0 + erow;
    const int ub   = (n0 >> 2) + q * 2;
    float creg0 = c0[grow * HID + ub];
    float creg1 = c0[grow * HID + ub + 1];
    __syncthreads();

    int sense = 0;
    for (int s = 0; s < S_LEN; s++){
        const __half* hsrc = g_hh[s & 1];

        const float* xpr = g_xp + ((size_t)s * NBATCH + grow) * GDIM + n0 + q * 8;
        float4 xv0 = *reinterpret_cast<const float4*>(xpr);
        float4 xv1 = *reinterpret_cast<const float4*>(xpr + 4);

        // parity-split accumulators: [kkl&1][nt] -> 4 independent chains/warp
        float acc[2][2][4];
        #pragma unroll
        for (int p = 0; p < 2; p++)
            #pragma unroll
            for (int j = 0; j < 2; j++)
                #pragma unroll
                for (int k = 0; k < 4; k++) acc[p][j][k] = 0.0f;

        load_chunk(abase + 0 * CHB, hsrc, m0, 0, tid); CP_COMMIT();
        load_chunk(abase + 1 * CHB, hsrc, m0, 1, tid); CP_COMMIT();

        for (int kt = 0; kt < NCH; kt++){
            if (kt + 2 < NCH){
                load_chunk(abase + ((kt + 2) % 3) * CHB, hsrc, m0, kt + 2, tid);
                CP_COMMIT();
                CP_WAIT(2);
            } else if (kt == NCH - 2){
                CP_WAIT(1);
            } else {
                CP_WAIT(0);
            }
            __syncthreads();

            const unsigned ab = abase + (kt % 3) * CHB;
            #pragma unroll
            for (int kkl = 0; kkl < 16; kkl++){
                const int par  = kkl & 1;
                const int lrow = lane & 15;
                const int koff = kkl * 16 + ((lane >> 4) << 3);
                const int c16  = koff >> 3;
                unsigned ah[4];
                {
                    int r = warp_m * 16 + lrow;
                    ldmx4(ah, ab + r * 512 + ((((c16 ^ r) & 7) | (c16 & 24)) << 4));
                }
                unsigned b[2][2];
                {
                    int r = warp_n * 16 + lrow;
                    int c8 = (kt * 256 + koff) >> 3;
                    unsigned t4[4];
                    ldmx4(t4, wbase + r * 2048 + (((c8 & ~7) | ((c8 ^ r) & 7)) << 4));
                    b[0][0] = t4[0]; b[1][0] = t4[1]; b[0][1] = t4[2]; b[1][1] = t4[3];
                }
                #pragma unroll
                for (int nt = 0; nt < 2; nt++)
                    mma_f16(acc[par][nt], ah, b[nt]);
            }
            __syncthreads();
        }

        // stage gates (16KB in stage-0 buffer), summing the parity halves
        float* gates = (float*)(dyn + OFF_A);
        #pragma unroll
        for (int nt = 0; nt < 2; nt++)
            #pragma unroll
            for (int pp = 0; pp < 2; pp++){
                int row = warp_m * 16 + (lane >> 2) + 8 * pp;
                int col = warp_n * 16 + nt * 8 + 2 * (lane & 3);
                gates[row * 64 + col]     = acc[0][nt][2 * pp]     + acc[1][nt][2 * pp];
                gates[row * 64 + col + 1] = acc[0][nt][2 * pp + 1] + acc[1][nt][2 * pp + 1];
            }
        __syncthreads();

        {
            const float* gr = &gates[erow * 64 + q * 8];
            float4 g0 = *reinterpret_cast<const float4*>(gr);
            float4 g1 = *reinterpret_cast<const float4*>(gr + 4);

            float ig = sigmoidf_(g0.x + xv0.x);
            float fg = sigmoidf_(g0.y + xv0.y);
            float gg = tanhf    (g0.z + xv0.z);
            float og = sigmoidf_(g0.w + xv0.w);
            creg0 = fg * creg0 + ig * gg;
            float hv0 = og * tanhf(creg0);

            ig = sigmoidf_(g1.x + xv1.x);
            fg = sigmoidf_(g1.y + xv1.y);
            gg = tanhf    (g1.z + xv1.z);
            og = sigmoidf_(g1.w + xv1.w);
            creg1 = fg * creg1 + ig * gg;
            float hv1 = og * tanhf(creg1);

            *reinterpret_cast<__half2*>(&g_hh[(s + 1) & 1][grow * HID + ub]) =
                __halves2half2(__float2half_rn(hv0), __float2half_rn(hv1));
        }

        grid_barrier(&sense);
    }
}

// ---------------- decode (1024 threads, 8-way K split) ----------------
__global__ void lstm_decode(const float* __restrict__ W_dec, const float* __restrict__ b_dec,
                            float* __restrict__ out){
    __shared__ float wsh[NOUT * HID];
    __shared__ float lsh[NOUT * NBATCH];
    __shared__ float red[2 * NOUT];
    int tid = threadIdx.x;
    for (int i = tid; i < NOUT * HID; i += 1024) wsh[i] = W_dec[i];
    __syncthreads();
    int b = tid >> 3, kseg = tid & 7;
    const uint4* hp = reinterpret_cast<const uint4*>(&g_hh[0][b * HID + kseg * 128]);
    float a[4] = {0.f, 0.f, 0.f, 0.f};
    #pragma unroll 4
    for (int v = 0; v < 16; v++){
        uint4 pk = hp[v];
        const __half* h8 = reinterpret_cast<const __half*>(&pk);
        #pragma unroll
        for (int e = 0; e < 8; e++){
            float hv = __half2float(h8[e]);
            int kk = kseg * 128 + v * 8 + e;
            a[0] += hv * wsh[kk];
            a[1] += hv * wsh[HID + kk];
            a[2] += hv * wsh[2 * HID + kk];
            a[3] += hv * wsh[3 * HID + kk];
        }
    }
    #pragma unroll
    for (int o = 0; o < 4; o++){
        a[o] += __shfl_xor_sync(0xFFFFFFFFu, a[o], 1);
        a[o] += __shfl_xor_sync(0xFFFFFFFFu, a[o], 2);
        a[o] += __shfl_xor_sync(0xFFFFFFFFu, a[o], 4);
    }
    if (kseg == 0){
        #pragma unroll
        for (int o = 0; o < 4; o++) lsh[o * NBATCH + b] = a[o] + b_dec[o];
    }
    __syncthreads();
    if (tid < NOUT){
        int o = tid;
        float m = -1e30f;
        for (int j = 0; j < NBATCH; j++) m = fmaxf(m, lsh[o * NBATCH + j]);
        float sum = 0.0f;
        for (int j = 0; j < NBATCH; j++) sum += expf(lsh[o * NBATCH + j] - m);
        red[o] = m; red[NOUT + o] = sum;
    }
    __syncthreads();
    if (tid < NBATCH){
        #pragma unroll
        for (int o = 0; o < NOUT; o++)
            out[tid * NOUT + o] = expf(lsh[o * NBATCH + tid] - red[o]) / red[NOUT + o];
    }
}

// ---------------- launch ----------------
extern "C" void kernel_launch(void* const* d_in, const int* in_sizes, int n_in,
                              void* d_out, int out_size)
{
    const float* inputs = (const float*)d_in[0];
    const float* h0     = (const float*)d_in[1];
    const float* c0     = (const float*)d_in[2];
    const float* W_ih   = (const float*)d_in[3];
    const float* W_hh   = (const float*)d_in[4];
    const float* b_ih   = (const float*)d_in[5];
    const float* b_hh   = (const float*)d_in[6];
    const float* W_dec  = (const float*)d_in[7];
    const float* b_dec  = (const float*)d_in[8];
    float* out = (float*)d_out;

    cudaFuncSetAttribute(lstm_rec, cudaFuncAttributeMaxDynamicSharedMemorySize, DYN_B);

    {
        int n8 = (S_LEN * NBATCH * IN_DIM) / 8;
        cvt_inputs<<<(n8 + 255) / 256, 256>>>(inputs);
        int nw = GDIM * (IN_DIM / 4);
        cvt_wih<<<(nw + 255) / 256, 256>>>(W_ih, b_ih, b_hh, h0);
    }

    dim3 g1(GDIM / BN, (S_LEN * NBATCH) / BM);
    xproj_gemm<<<g1, NTHREADS>>>();

    lstm_rec<<<PGRID, PTH, DYN_B>>>(W_hh, c0);

    lstm_decode<<<1, 1024>>>(W_dec, b_dec, out);
}

// round 11
// speedup vs baseline: 1.2555x; 1.2098x over previous
#include <cuda_runtime.h>
#include <cuda_bf16.h>
#include <cuda_fp16.h>
#include <math.h>
#include <stdint.h>

#define S_LEN   512
#define NBATCH  128
#define IN_DIM  512
#define HID     1024
#define GDIM    4096   // interleaved: col g -> gate g&3, unit g>>2
#define NOUT    4

// phase-1 tiling: 128x128 tiles, BK=64, 3-stage cp.async
#define BM 128
#define BN 128
#define BKP 64
#define P1TH 256
#define P1STG_B 32768            // stage: A 16KB + B 16KB
#define P1DYN (3 * P1STG_B)      // 98304

// recurrence: 128 CTAs = 2 row-halves x 64 col-tiles, each 64x64xK (R7-proven)
#define PGRID 128
#define PTH 512
#define NCH 4                    // K chunks of 256
#define CHB 32768                // chunk: 64 rows x 512B
#define WB  131072               // W: 64 gate-cols x 2048B
#define OFF_W 0
#define OFF_A WB
#define DYN_B (WB + 3 * CHB)     // 229376

__device__ __half g_xp[(size_t)S_LEN * NBATCH * GDIM];   // x_proj (+bias), fp16
__device__ __half g_xh[(size_t)S_LEN * NBATCH * IN_DIM]; // inputs fp16
__device__ __half g_wih[(size_t)GDIM * IN_DIM];          // gathered W_ih fp16
__device__ float  g_bias[GDIM];                          // gathered b_ih+b_hh
__device__ __half g_hh[2][NBATCH * HID];                 // hidden fp16, dbl-buffered
__device__ int g_bar_count;
__device__ volatile int g_bar_phase;

__device__ __forceinline__ unsigned su32(const void* p){
    return (unsigned)__cvta_generic_to_shared(p);
}
__device__ __forceinline__ float sigmoidf_(float x){ return 1.0f / (1.0f + expf(-x)); }
__device__ __forceinline__ void cpasync16(unsigned saddr, const void* g){
    asm volatile("cp.async.cg.shared.global [%0], [%1], 16;" :: "r"(saddr), "l"(g));
}
#define CP_COMMIT() asm volatile("cp.async.commit_group;")
#define CP_WAIT(n)  asm volatile("cp.async.wait_group %0;" :: "n"(n))

__device__ __forceinline__ void ldmx4(unsigned* r, unsigned addr){
    asm volatile("ldmatrix.sync.aligned.m8n8.x4.shared.b16 {%0,%1,%2,%3}, [%4];"
        : "=r"(r[0]), "=r"(r[1]), "=r"(r[2]), "=r"(r[3]) : "r"(addr));
}
__device__ __forceinline__ void mma_f16(float* d, const unsigned* a, const unsigned* b){
    asm volatile("mma.sync.aligned.m16n8k16.row.col.f32.f16.f16.f32 "
        "{%0,%1,%2,%3},{%4,%5,%6,%7},{%8,%9},{%0,%1,%2,%3};"
        : "+f"(d[0]), "+f"(d[1]), "+f"(d[2]), "+f"(d[3])
        : "r"(a[0]), "r"(a[1]), "r"(a[2]), "r"(a[3]), "r"(b[0]), "r"(b[1]));
}

// full grid barrier (R7-proven)
__device__ __forceinline__ void grid_barrier(int* sense){
    __threadfence();
    __syncthreads();
    if (threadIdx.x == 0){
        int target = *sense ^ 1;
        if (atomicAdd(&g_bar_count, 1) == PGRID - 1){
            atomicExch(&g_bar_count, 0);
            __threadfence();
            g_bar_phase = target;
        } else {
            while (g_bar_phase != target) __nanosleep(40);
        }
        *sense = target;
    }
    __syncthreads();
    __threadfence();
}

// ---------------- conversion pre-kernels ----------------
__global__ void cvt_inputs(const float* __restrict__ in){
    size_t i = (size_t)(blockIdx.x * blockDim.x + threadIdx.x) * 8;
    if (i < (size_t)S_LEN * NBATCH * IN_DIM){
        float4 v0 = *reinterpret_cast<const float4*>(in + i);
        float4 v1 = *reinterpret_cast<const float4*>(in + i + 4);
        __half2* d = reinterpret_cast<__half2*>(&g_xh[i]);
        d[0] = __floats2half2_rn(v0.x, v0.y);
        d[1] = __floats2half2_rn(v0.z, v0.w);
        d[2] = __floats2half2_rn(v1.x, v1.y);
        d[3] = __floats2half2_rn(v1.z, v1.w);
    }
}
__global__ void cvt_wih(const float* __restrict__ W_ih,
                        const float* __restrict__ b_ih, const float* __restrict__ b_hh,
                        const float* __restrict__ h0){
    int idx = blockIdx.x * blockDim.x + threadIdx.x;
    if (idx < GDIM * (IN_DIM / 4)){
        int g = idx >> 7;
        int c = (idx & 127) * 4;
        int r = (g & 3) * HID + (g >> 2);
        float4 v = *reinterpret_cast<const float4*>(W_ih + (size_t)r * IN_DIM + c);
        __half2* d = reinterpret_cast<__half2*>(&g_wih[(size_t)g * IN_DIM + c]);
        d[0] = __floats2half2_rn(v.x, v.y);
        d[1] = __floats2half2_rn(v.z, v.w);
        if (c == 0) g_bias[g] = b_ih[r] + b_hh[r];
    }
    if (idx < NBATCH * HID) g_hh[0][idx] = __float2half_rn(h0[idx]);
    if (idx == 0){ g_bar_count = 0; g_bar_phase = 0; }
}

// ---------------- phase 1: x_proj 128x128, 3-stage cp.async, 1 sync/iter ----------------
// smem stage layout: A rows then B rows; row = 64 fp16 = 128B, 8 16B-chunks,
// chunk c at row r swizzled to c ^ (r&7).
__global__ __launch_bounds__(P1TH)
void xproj_gemm()
{
    extern __shared__ __align__(1024) char p1s[];
    const int tid = threadIdx.x, lane = tid & 31, wid = tid >> 5;
    const int warp_m = wid & 3;     // 0..3 : 32 rows
    const int warp_n = wid >> 2;    // 0..1 : 64 cols
    const int m0 = blockIdx.y * BM, n0 = blockIdx.x * BN;
    const unsigned sbase = su32(p1s);

    float acc[2][4][2][4];   // [mt][nb][nt][4]
    #pragma unroll
    for (int a = 0; a < 2; a++)
        #pragma unroll
        for (int b = 0; b < 4; b++)
            #pragma unroll
            for (int c = 0; c < 2; c++)
                #pragma unroll
                for (int d = 0; d < 4; d++) acc[a][b][c][d] = 0.0f;

    // load mapping: 2048 16B-chunks per stage (A 1024 + B 1024), 8 per thread
    int pr[8], pc[8], ppart[8];
    const __half* gsrc[8];
    #pragma unroll
    for (int i = 0; i < 8; i++){
        int idx = tid + i * P1TH;
        ppart[i] = idx >> 10;            // 0=A, 1=B
        int w = idx & 1023;
        pr[i] = w >> 3;                  // row 0..127
        pc[i] = w & 7;                   // 16B chunk 0..7
        gsrc[i] = ppart[i] ? (g_wih + (size_t)(n0 + pr[i]) * IN_DIM + pc[i] * 8)
                           : (g_xh  + (size_t)(m0 + pr[i]) * IN_DIM + pc[i] * 8);
    }

    // prologue: stages 0,1
    #pragma unroll
    for (int st = 0; st < 2; st++){
        #pragma unroll
        for (int i = 0; i < 8; i++){
            unsigned dst = sbase + st * P1STG_B + ppart[i] * 16384
                         + pr[i] * 128 + ((pc[i] ^ (pr[i] & 7)) << 4);
            cpasync16(dst, gsrc[i] + st * BKP);
        }
        CP_COMMIT();
    }

    const int KIT = IN_DIM / BKP;   // 8
    for (int kt = 0; kt < KIT; kt++){
        if (kt + 1 < KIT) CP_WAIT(1); else CP_WAIT(0);
        __syncthreads();

        // refill the stage retired last iteration (protected by the sync above)
        if (kt + 2 < KIT){
            int st = (kt + 2) % 3;
            #pragma unroll
            for (int i = 0; i < 8; i++){
                unsigned dst = sbase + st * P1STG_B + ppart[i] * 16384
                             + pr[i] * 128 + ((pc[i] ^ (pr[i] & 7)) << 4);
                cpasync16(dst, gsrc[i] + (kt + 2) * BKP);
            }
            CP_COMMIT();
        }

        const unsigned ab = sbase + (kt % 3) * P1STG_B;
        const unsigned bb = ab + 16384;
        #pragma unroll
        for (int kk = 0; kk < 4; kk++){
            const int lrow = lane & 15;
            const int cc = (kk * 16 + ((lane >> 4) << 3)) >> 3;   // chunk 0..7
            unsigned ah[2][4];
            #pragma unroll
            for (int mt = 0; mt < 2; mt++){
                int r = warp_m * 32 + mt * 16 + lrow;
                ldmx4(ah[mt], ab + r * 128 + ((cc ^ (r & 7)) << 4));
            }
            #pragma unroll
            for (int nb = 0; nb < 4; nb++){
                int r = warp_n * 64 + nb * 16 + lrow;
                unsigned t4[4], b[2][2];
                ldmx4(t4, bb + r * 128 + ((cc ^ (r & 7)) << 4));
                b[0][0] = t4[0]; b[1][0] = t4[1]; b[0][1] = t4[2]; b[1][1] = t4[3];
                #pragma unroll
                for (int mt = 0; mt < 2; mt++)
                    #pragma unroll
                    for (int nt = 0; nt < 2; nt++)
                        mma_f16(acc[mt][nb][nt], ah[mt], b[nt]);
            }
        }
    }

    // epilogue: add bias, store fp16
    #pragma unroll
    for (int mt = 0; mt < 2; mt++)
        #pragma unroll
        for (int nb = 0; nb < 4; nb++)
            #pragma unroll
            for (int nt = 0; nt < 2; nt++)
                #pragma unroll
                for (int pp = 0; pp < 2; pp++){
                    int row = m0 + warp_m * 32 + mt * 16 + (lane >> 2) + 8 * pp;
                    int col = n0 + warp_n * 64 + nb * 16 + nt * 8 + 2 * (lane & 3);
                    float v0 = acc[mt][nb][nt][2 * pp]     + g_bias[col];
                    float v1 = acc[mt][nb][nt][2 * pp + 1] + g_bias[col + 1];
                    *reinterpret_cast<__half2*>(&g_xp[(size_t)row * GDIM + col]) =
                        __floats2half2_rn(v0, v1);
                }
}

// ---------------- persistent recurrence (exact R7 form, fp16 xp reads) ----------------
__device__ __forceinline__ void load_chunk(unsigned abase_st, const __half* hsrc,
                                           int m0, int kt, int tid){
    #pragma unroll
    for (int i = 0; i < 4; i++){
        int u = tid + i * PTH;
        int r = u >> 5;
        int c16 = u & 31;
        const __half* src = hsrc + (size_t)(m0 + r) * HID + kt * 256 + c16 * 8;
        unsigned dst = abase_st + r * 512 + ((((c16 ^ r) & 7) | (c16 & 24)) << 4);
        cpasync16(dst, src);
    }
}

__global__ __launch_bounds__(PTH, 1)
void lstm_rec(const float* __restrict__ W_hh, const float* __restrict__ c0)
{
    extern __shared__ __align__(1024) char dyn[];
    const int tid  = threadIdx.x;
    const int lane = tid & 31;
    const int wid  = tid >> 5;
    const int warp_m = wid >> 2;
    const int warp_n = wid & 3;
    const int m0 = (blockIdx.x & 1) * 64;
    const int n0 = (blockIdx.x >> 1) * 64;
    const unsigned wbase = su32(dyn + OFF_W);
    const unsigned abase = su32(dyn + OFF_A);

    for (int idx = tid; idx < 64 * (HID / 8); idx += PTH){
        int j  = idx >> 7;
        int c8 = idx & 127;
        int c  = c8 * 8;
        int g  = n0 + j;
        const float* src = W_hh + (size_t)((g & 3) * HID + (g >> 2)) * HID + c;
        float4 v0 = *reinterpret_cast<const float4*>(src);
        float4 v1 = *reinterpret_cast<const float4*>(src + 4);
        int sc = (c8 & ~7) | ((c8 ^ j) & 7);
        __half2* d = reinterpret_cast<__half2*>(dyn + OFF_W + j * 2048 + (sc << 4));
        d[0] = __floats2half2_rn(v0.x, v0.y);
        d[1] = __floats2half2_rn(v0.z, v0.w);
        d[2] = __floats2half2_rn(v1.x, v1.y);
        d[3] = __floats2half2_rn(v1.z, v1.w);
    }

    const int erow = tid >> 3;
    const int q    = tid & 7;
    const int grow = m0 + erow;
    const int ub   = (n0 >> 2) + q * 2;
    float creg0 = c0[grow * HID + ub];
    float creg1 = c0[grow * HID + ub + 1];
    __syncthreads();

    int sense = 0;
    for (int s = 0; s < S_LEN; s++){
        const __half* hsrc = g_hh[s & 1];

        // prefetch x_proj segment (8 fp16 = one uint4)
        const __half* xpr = g_xp + ((size_t)s * NBATCH + grow) * GDIM + n0 + q * 8;
        uint4 xpk = *reinterpret_cast<const uint4*>(xpr);

        float acc[2][4];
        #pragma unroll
        for (int j = 0; j < 2; j++)
            #pragma unroll
            for (int k = 0; k < 4; k++) acc[j][k] = 0.0f;

        load_chunk(abase + 0 * CHB, hsrc, m0, 0, tid); CP_COMMIT();
        load_chunk(abase + 1 * CHB, hsrc, m0, 1, tid); CP_COMMIT();

        for (int kt = 0; kt < NCH; kt++){
            if (kt + 2 < NCH){
                load_chunk(abase + ((kt + 2) % 3) * CHB, hsrc, m0, kt + 2, tid);
                CP_COMMIT();
                CP_WAIT(2);
            } else if (kt == NCH - 2){
                CP_WAIT(1);
            } else {
                CP_WAIT(0);
            }
            __syncthreads();

            const unsigned ab = abase + (kt % 3) * CHB;
            #pragma unroll
            for (int kkl = 0; kkl < 16; kkl++){
                const int lrow = lane & 15;
                const int koff = kkl * 16 + ((lane >> 4) << 3);
                const int c16  = koff >> 3;
                unsigned ah[4];
                {
                    int r = warp_m * 16 + lrow;
                    ldmx4(ah, ab + r * 512 + ((((c16 ^ r) & 7) | (c16 & 24)) << 4));
                }
                unsigned b[2][2];
                {
                    int r = warp_n * 16 + lrow;
                    int c8 = (kt * 256 + koff) >> 3;
                    unsigned t4[4];
                    ldmx4(t4, wbase + r * 2048 + (((c8 & ~7) | ((c8 ^ r) & 7)) << 4));
                    b[0][0] = t4[0]; b[1][0] = t4[1]; b[0][1] = t4[2]; b[1][1] = t4[3];
                }
                #pragma unroll
                for (int nt = 0; nt < 2; nt++)
                    mma_f16(acc[nt], ah, b[nt]);
            }
            __syncthreads();
        }

        // stage gates (16KB in stage-0 buffer)
        float* gates = (float*)(dyn + OFF_A);
        #pragma unroll
        for (int nt = 0; nt < 2; nt++)
            #pragma unroll
            for (int pp = 0; pp < 2; pp++){
                int row = warp_m * 16 + (lane >> 2) + 8 * pp;
                int col = warp_n * 16 + nt * 8 + 2 * (lane & 3);
                gates[row * 64 + col]     = acc[nt][2 * pp];
                gates[row * 64 + col + 1] = acc[nt][2 * pp + 1];
            }
        __syncthreads();

        {
            const __half2* xh2 = reinterpret_cast<const __half2*>(&xpk);
            float2 x0 = __half22float2(xh2[0]);
            float2 x1 = __half22float2(xh2[1]);
            float2 x2 = __half22float2(xh2[2]);
            float2 x3 = __half22float2(xh2[3]);

            const float* gr = &gates[erow * 64 + q * 8];
            float4 g0 = *reinterpret_cast<const float4*>(gr);
            float4 g1 = *reinterpret_cast<const float4*>(gr + 4);

            float ig = sigmoidf_(g0.x + x0.x);
            float fg = sigmoidf_(g0.y + x0.y);
            float gg = tanhf    (g0.z + x1.x);
            float og = sigmoidf_(g0.w + x1.y);
            creg0 = fg * creg0 + ig * gg;
            float hv0 = og * tanhf(creg0);

            ig = sigmoidf_(g1.x + x2.x);
            fg = sigmoidf_(g1.y + x2.y);
            gg = tanhf    (g1.z + x3.x);
            og = sigmoidf_(g1.w + x3.y);
            creg1 = fg * creg1 + ig * gg;
            float hv1 = og * tanhf(creg1);

            *reinterpret_cast<__half2*>(&g_hh[(s + 1) & 1][grow * HID + ub]) =
                __halves2half2(__float2half_rn(hv0), __float2half_rn(hv1));
        }

        grid_barrier(&sense);
    }
}

// ---------------- decode (1024 threads, 8-way K split) ----------------
__global__ void lstm_decode(const float* __restrict__ W_dec, const float* __restrict__ b_dec,
                            float* __restrict__ out){
    __shared__ float wsh[NOUT * HID];
    __shared__ float lsh[NOUT * NBATCH];
    __shared__ float red[2 * NOUT];
    int tid = threadIdx.x;
    for (int i = tid; i < NOUT * HID; i += 1024) wsh[i] = W_dec[i];
    __syncthreads();
    int b = tid >> 3, kseg = tid & 7;
    const uint4* hp = reinterpret_cast<const uint4*>(&g_hh[0][b * HID + kseg * 128]);
    float a[4] = {0.f, 0.f, 0.f, 0.f};
    #pragma unroll 4
    for (int v = 0; v < 16; v++){
        uint4 pk = hp[v];
        const __half* h8 = reinterpret_cast<const __half*>(&pk);
        #pragma unroll
        for (int e = 0; e < 8; e++){
            float hv = __half2float(h8[e]);
            int kk = kseg * 128 + v * 8 + e;
            a[0] += hv * wsh[kk];
            a[1] += hv * wsh[HID + kk];
            a[2] += hv * wsh[2 * HID + kk];
            a[3] += hv * wsh[3 * HID + kk];
        }
    }
    #pragma unroll
    for (int o = 0; o < 4; o++){
        a[o] += __shfl_xor_sync(0xFFFFFFFFu, a[o], 1);
        a[o] += __shfl_xor_sync(0xFFFFFFFFu, a[o], 2);
        a[o] += __shfl_xor_sync(0xFFFFFFFFu, a[o], 4);
    }
    if (kseg == 0){
        #pragma unroll
        for (int o = 0; o < 4; o++) lsh[o * NBATCH + b] = a[o] + b_dec[o];
    }
    __syncthreads();
    if (tid < NOUT){
        int o = tid;
        float m = -1e30f;
        for (int j = 0; j < NBATCH; j++) m = fmaxf(m, lsh[o * NBATCH + j]);
        float sum = 0.0f;
        for (int j = 0; j < NBATCH; j++) sum += expf(lsh[o * NBATCH + j] - m);
        red[o] = m; red[NOUT + o] = sum;
    }
    __syncthreads();
    if (tid < NBATCH){
        #pragma unroll
        for (int o = 0; o < NOUT; o++)
            out[tid * NOUT + o] = expf(lsh[o * NBATCH + tid] - red[o]) / red[NOUT + o];
    }
}

// ---------------- launch ----------------
extern "C" void kernel_launch(void* const* d_in, const int* in_sizes, int n_in,
                              void* d_out, int out_size)
{
    const float* inputs = (const float*)d_in[0];
    const float* h0     = (const float*)d_in[1];
    const float* c0     = (const float*)d_in[2];
    const float* W_ih   = (const float*)d_in[3];
    const float* W_hh   = (const float*)d_in[4];
    const float* b_ih   = (const float*)d_in[5];
    const float* b_hh   = (const float*)d_in[6];
    const float* W_dec  = (const float*)d_in[7];
    const float* b_dec  = (const float*)d_in[8];
    float* out = (float*)d_out;

    cudaFuncSetAttribute(lstm_rec, cudaFuncAttributeMaxDynamicSharedMemorySize, DYN_B);
    cudaFuncSetAttribute(xproj_gemm, cudaFuncAttributeMaxDynamicSharedMemorySize, P1DYN);

    {
        int n8 = (S_LEN * NBATCH * IN_DIM) / 8;
        cvt_inputs<<<(n8 + 255) / 256, 256>>>(inputs);
        int nw = GDIM * (IN_DIM / 4);
        cvt_wih<<<(nw + 255) / 256, 256>>>(W_ih, b_ih, b_hh, h0);
    }

    dim3 g1(GDIM / BN, (S_LEN * NBATCH) / BM);   // 32 x 512
    xproj_gemm<<<g1, P1TH, P1DYN>>>();

    lstm_rec<<<PGRID, PTH, DYN_B>>>(W_hh, c0);

    lstm_decode<<<1, 1024>>>(W_dec, b_dec, out);
}

// round 12
// speedup vs baseline: 1.3039x; 1.0386x over previous
#include <cuda_runtime.h>
#include <cuda_bf16.h>
#include <cuda_fp16.h>
#include <math.h>
#include <stdint.h>

#define S_LEN   512
#define NBATCH  128
#define IN_DIM  512
#define HID     1024
#define GDIM    4096   // interleaved: col g -> gate g&3, unit g>>2
#define NOUT    4

// phase-1 tiling: 128x128 tiles, BK=64, 3-stage cp.async (R11-proven)
#define BM 128
#define BN 128
#define BKP 64
#define P1TH 256
#define P1STG_B 32768
#define P1DYN (3 * P1STG_B)

// recurrence: 128 CTAs = 2 row-halves x 64 col-tiles, each 64x64xK
#define PGRID 128
#define PTH 512
#define NCH 4                    // K chunks of 256
#define CHB 32768                // chunk: 64 rows x 512B
#define WB  131072               // W: 64 gate-cols x 2048B
#define OFF_W 0
#define OFF_A WB
#define DYN_B (WB + 3 * CHB)     // 229376

__device__ __half g_xp[(size_t)S_LEN * NBATCH * GDIM];   // x_proj (+bias), fp16
__device__ __half g_xh[(size_t)S_LEN * NBATCH * IN_DIM]; // inputs fp16
__device__ __half g_wih[(size_t)GDIM * IN_DIM];          // gathered W_ih fp16
__device__ float  g_bias[GDIM];                          // gathered b_ih+b_hh
__device__ __half g_hh[2][NBATCH * HID];                 // hidden fp16, dbl-buffered
__device__ int g_flag[PGRID * 32];                       // per-CTA step flag, 1 line each

__device__ __forceinline__ unsigned su32(const void* p){
    return (unsigned)__cvta_generic_to_shared(p);
}
__device__ __forceinline__ float sigmoidf_(float x){ return 1.0f / (1.0f + expf(-x)); }
__device__ __forceinline__ void cpasync16(unsigned saddr, const void* g){
    asm volatile("cp.async.cg.shared.global [%0], [%1], 16;" :: "r"(saddr), "l"(g));
}
#define CP_COMMIT() asm volatile("cp.async.commit_group;")
#define CP_WAIT(n)  asm volatile("cp.async.wait_group %0;" :: "n"(n))

__device__ __forceinline__ void ldmx4(unsigned* r, unsigned addr){
    asm volatile("ldmatrix.sync.aligned.m8n8.x4.shared.b16 {%0,%1,%2,%3}, [%4];"
        : "=r"(r[0]), "=r"(r[1]), "=r"(r[2]), "=r"(r[3]) : "r"(addr));
}
__device__ __forceinline__ void mma_f16(float* d, const unsigned* a, const unsigned* b){
    asm volatile("mma.sync.aligned.m16n8k16.row.col.f32.f16.f16.f32 "
        "{%0,%1,%2,%3},{%4,%5,%6,%7},{%8,%9},{%0,%1,%2,%3};"
        : "+f"(d[0]), "+f"(d[1]), "+f"(d[2]), "+f"(d[3])
        : "r"(a[0]), "r"(a[1]), "r"(a[2]), "r"(a[3]), "r"(b[0]), "r"(b[1]));
}

// warp-0 poll: chunk ch of the caller's half needs col-tiles [16ch,16ch+16) at flag >= tgt
__device__ __forceinline__ void flag_poll16(int ch, int tgt, int half, int lane){
    if (lane < 16){
        const volatile int* f = &g_flag[(((ch << 4) + lane) * 2 + half) * 32];
        while (*f < tgt) __nanosleep(64);
    }
    __syncwarp();
}

// ---------------- conversion pre-kernels ----------------
__global__ void cvt_inputs(const float* __restrict__ in){
    size_t i = (size_t)(blockIdx.x * blockDim.x + threadIdx.x) * 8;
    if (i < (size_t)S_LEN * NBATCH * IN_DIM){
        float4 v0 = *reinterpret_cast<const float4*>(in + i);
        float4 v1 = *reinterpret_cast<const float4*>(in + i + 4);
        __half2* d = reinterpret_cast<__half2*>(&g_xh[i]);
        d[0] = __floats2half2_rn(v0.x, v0.y);
        d[1] = __floats2half2_rn(v0.z, v0.w);
        d[2] = __floats2half2_rn(v1.x, v1.y);
        d[3] = __floats2half2_rn(v1.z, v1.w);
    }
}
__global__ void cvt_wih(const float* __restrict__ W_ih,
                        const float* __restrict__ b_ih, const float* __restrict__ b_hh,
                        const float* __restrict__ h0){
    int idx = blockIdx.x * blockDim.x + threadIdx.x;
    if (idx < GDIM * (IN_DIM / 4)){
        int g = idx >> 7;
        int c = (idx & 127) * 4;
        int r = (g & 3) * HID + (g >> 2);
        float4 v = *reinterpret_cast<const float4*>(W_ih + (size_t)r * IN_DIM + c);
        __half2* d = reinterpret_cast<__half2*>(&g_wih[(size_t)g * IN_DIM + c]);
        d[0] = __floats2half2_rn(v.x, v.y);
        d[1] = __floats2half2_rn(v.z, v.w);
        if (c == 0) g_bias[g] = b_ih[r] + b_hh[r];
    }
    if (idx < NBATCH * HID) g_hh[0][idx] = __float2half_rn(h0[idx]);
    if (idx < PGRID) g_flag[idx * 32] = 0;
}

// ---------------- phase 1: x_proj 128x128, 3-stage cp.async (R11-proven) ----------------
__global__ __launch_bounds__(P1TH)
void xproj_gemm()
{
    extern __shared__ __align__(1024) char p1s[];
    const int tid = threadIdx.x, lane = tid & 31, wid = tid >> 5;
    const int warp_m = wid & 3;
    const int warp_n = wid >> 2;
    const int m0 = blockIdx.y * BM, n0 = blockIdx.x * BN;
    const unsigned sbase = su32(p1s);

    float acc[2][4][2][4];
    #pragma unroll
    for (int a = 0; a < 2; a++)
        #pragma unroll
        for (int b = 0; b < 4; b++)
            #pragma unroll
            for (int c = 0; c < 2; c++)
                #pragma unroll
                for (int d = 0; d < 4; d++) acc[a][b][c][d] = 0.0f;

    int pr[8], pc[8], ppart[8];
    const __half* gsrc[8];
    #pragma unroll
    for (int i = 0; i < 8; i++){
        int idx = tid + i * P1TH;
        ppart[i] = idx >> 10;
        int w = idx & 1023;
        pr[i] = w >> 3;
        pc[i] = w & 7;
        gsrc[i] = ppart[i] ? (g_wih + (size_t)(n0 + pr[i]) * IN_DIM + pc[i] * 8)
                           : (g_xh  + (size_t)(m0 + pr[i]) * IN_DIM + pc[i] * 8);
    }

    #pragma unroll
    for (int st = 0; st < 2; st++){
        #pragma unroll
        for (int i = 0; i < 8; i++){
            unsigned dst = sbase + st * P1STG_B + ppart[i] * 16384
                         + pr[i] * 128 + ((pc[i] ^ (pr[i] & 7)) << 4);
            cpasync16(dst, gsrc[i] + st * BKP);
        }
        CP_COMMIT();
    }

    const int KIT = IN_DIM / BKP;
    for (int kt = 0; kt < KIT; kt++){
        if (kt + 1 < KIT) CP_WAIT(1); else CP_WAIT(0);
        __syncthreads();

        if (kt + 2 < KIT){
            int st = (kt + 2) % 3;
            #pragma unroll
            for (int i = 0; i < 8; i++){
                unsigned dst = sbase + st * P1STG_B + ppart[i] * 16384
                             + pr[i] * 128 + ((pc[i] ^ (pr[i] & 7)) << 4);
                cpasync16(dst, gsrc[i] + (kt + 2) * BKP);
            }
            CP_COMMIT();
        }

        const unsigned ab = sbase + (kt % 3) * P1STG_B;
        const unsigned bb = ab + 16384;
        #pragma unroll
        for (int kk = 0; kk < 4; kk++){
            const int lrow = lane & 15;
            const int cc = (kk * 16 + ((lane >> 4) << 3)) >> 3;
            unsigned ah[2][4];
            #pragma unroll
            for (int mt = 0; mt < 2; mt++){
                int r = warp_m * 32 + mt * 16 + lrow;
                ldmx4(ah[mt], ab + r * 128 + ((cc ^ (r & 7)) << 4));
            }
            #pragma unroll
            for (int nb = 0; nb < 4; nb++){
                int r = warp_n * 64 + nb * 16 + lrow;
                unsigned t4[4], b[2][2];
                ldmx4(t4, bb + r * 128 + ((cc ^ (r & 7)) << 4));
                b[0][0] = t4[0]; b[1][0] = t4[1]; b[0][1] = t4[2]; b[1][1] = t4[3];
                #pragma unroll
                for (int mt = 0; mt < 2; mt++)
                    #pragma unroll
                    for (int nt = 0; nt < 2; nt++)
                        mma_f16(acc[mt][nb][nt], ah[mt], b[nt]);
            }
        }
    }

    #pragma unroll
    for (int mt = 0; mt < 2; mt++)
        #pragma unroll
        for (int nb = 0; nb < 4; nb++)
            #pragma unroll
            for (int nt = 0; nt < 2; nt++)
                #pragma unroll
                for (int pp = 0; pp < 2; pp++){
                    int row = m0 + warp_m * 32 + mt * 16 + (lane >> 2) + 8 * pp;
                    int col = n0 + warp_n * 64 + nb * 16 + nt * 8 + 2 * (lane & 3);
                    float v0 = acc[mt][nb][nt][2 * pp]     + g_bias[col];
                    float v1 = acc[mt][nb][nt][2 * pp + 1] + g_bias[col + 1];
                    *reinterpret_cast<__half2*>(&g_xp[(size_t)row * GDIM + col]) =
                        __floats2half2_rn(v0, v1);
                }
}

// ---------------- persistent recurrence (dataflow flags, no global barrier) ----------------
__device__ __forceinline__ void load_chunk(unsigned abase_st, const __half* hsrc,
                                           int m0, int kt, int tid){
    #pragma unroll
    for (int i = 0; i < 4; i++){
        int u = tid + i * PTH;
        int r = u >> 5;
        int c16 = u & 31;
        const __half* src = hsrc + (size_t)(m0 + r) * HID + kt * 256 + c16 * 8;
        unsigned dst = abase_st + r * 512 + ((((c16 ^ r) & 7) | (c16 & 24)) << 4);
        cpasync16(dst, src);
    }
}

__global__ __launch_bounds__(PTH, 1)
void lstm_rec(const float* __restrict__ W_hh, const float* __restrict__ c0)
{
    extern __shared__ __align__(1024) char dyn[];
    const int tid  = threadIdx.x;
    const int lane = tid & 31;
    const int wid  = tid >> 5;
    const int warp_m = wid >> 2;
    const int warp_n = wid & 3;
    const int half = blockIdx.x & 1;
    const int m0 = half * 64;
    const int n0 = (blockIdx.x >> 1) * 64;
    const int myflag = blockIdx.x * 32;
    const unsigned wbase = su32(dyn + OFF_W);
    const unsigned abase = su32(dyn + OFF_A);

    for (int idx = tid; idx < 64 * (HID / 8); idx += PTH){
        int j  = idx >> 7;
        int c8 = idx & 127;
        int c  = c8 * 8;
        int g  = n0 + j;
        const float* src = W_hh + (size_t)((g & 3) * HID + (g >> 2)) * HID + c;
        float4 v0 = *reinterpret_cast<const float4*>(src);
        float4 v1 = *reinterpret_cast<const float4*>(src + 4);
        int sc = (c8 & ~7) | ((c8 ^ j) & 7);
        __half2* d = reinterpret_cast<__half2*>(dyn + OFF_W + j * 2048 + (sc << 4));
        d[0] = __floats2half2_rn(v0.x, v0.y);
        d[1] = __floats2half2_rn(v0.z, v0.w);
        d[2] = __floats2half2_rn(v1.x, v1.y);
        d[3] = __floats2half2_rn(v1.z, v1.w);
    }

    const int erow = tid >> 3;
    const int q    = tid & 7;
    const int grow = m0 + erow;
    const int ub   = (n0 >> 2) + q * 2;
    float creg0 = c0[grow * HID + ub];
    float creg1 = c0[grow * HID + ub + 1];
    __syncthreads();

    for (int s = 0; s < S_LEN; s++){
        const __half* hsrc = g_hh[s & 1];

        // prefetch x_proj segment (8 fp16 = one uint4)
        const __half* xpr = g_xp + ((size_t)s * NBATCH + grow) * GDIM + n0 + q * 8;
        uint4 xpk = *reinterpret_cast<const uint4*>(xpr);

        float acc[2][4];
        #pragma unroll
        for (int j = 0; j < 2; j++)
            #pragma unroll
            for (int k = 0; k < 4; k++) acc[j][k] = 0.0f;

        // wait for chunk 0+1 producers (col-tiles 0..31 of this half), then load
        if (wid == 0 && lane < 32){
            const volatile int* f = &g_flag[(lane * 2 + half) * 32];
            while (*f < s) __nanosleep(64);
        }
        __syncthreads();
        load_chunk(abase + 0 * CHB, hsrc, m0, 0, tid); CP_COMMIT();
        load_chunk(abase + 1 * CHB, hsrc, m0, 1, tid); CP_COMMIT();

        for (int kt = 0; kt < NCH; kt++){
            if (kt + 2 < NCH){
                if (wid == 0) flag_poll16(kt + 2, s, half, lane);
                __syncthreads();   // releases poll; prior chunk's compute done by all
                load_chunk(abase + ((kt + 2) % 3) * CHB, hsrc, m0, kt + 2, tid);
                CP_COMMIT();
                CP_WAIT(2);
            } else if (kt == NCH - 2){
                CP_WAIT(1);
            } else {
                CP_WAIT(0);
            }
            __syncthreads();       // chunk kt data visible to all warps

            const unsigned ab = abase + (kt % 3) * CHB;
            #pragma unroll
            for (int kkl = 0; kkl < 16; kkl++){
                const int lrow = lane & 15;
                const int koff = kkl * 16 + ((lane >> 4) << 3);
                const int c16  = koff >> 3;
                unsigned ah[4];
                {
                    int r = warp_m * 16 + lrow;
                    ldmx4(ah, ab + r * 512 + ((((c16 ^ r) & 7) | (c16 & 24)) << 4));
                }
                unsigned b[2][2];
                {
                    int r = warp_n * 16 + lrow;
                    int c8 = (kt * 256 + koff) >> 3;
                    unsigned t4[4];
                    ldmx4(t4, wbase + r * 2048 + (((c8 & ~7) | ((c8 ^ r) & 7)) << 4));
                    b[0][0] = t4[0]; b[1][0] = t4[1]; b[0][1] = t4[2]; b[1][1] = t4[3];
                }
                #pragma unroll
                for (int nt = 0; nt < 2; nt++)
                    mma_f16(acc[nt], ah, b[nt]);
            }
        }
        __syncthreads();           // all compute done before gates overwrite stage 0

        // stage gates (16KB in stage-0 buffer)
        float* gates = (float*)(dyn + OFF_A);
        #pragma unroll
        for (int nt = 0; nt < 2; nt++)
            #pragma unroll
            for (int pp = 0; pp < 2; pp++){
                int row = warp_m * 16 + (lane >> 2) + 8 * pp;
                int col = warp_n * 16 + nt * 8 + 2 * (lane & 3);
                gates[row * 64 + col]     = acc[nt][2 * pp];
                gates[row * 64 + col + 1] = acc[nt][2 * pp + 1];
            }
        __syncthreads();

        {
            const __half2* xh2 = reinterpret_cast<const __half2*>(&xpk);
            float2 x0 = __half22float2(xh2[0]);
            float2 x1 = __half22float2(xh2[1]);
            float2 x2 = __half22float2(xh2[2]);
            float2 x3 = __half22float2(xh2[3]);

            const float* gr = &gates[erow * 64 + q * 8];
            float4 g0 = *reinterpret_cast<const float4*>(gr);
            float4 g1 = *reinterpret_cast<const float4*>(gr + 4);

            float ig = sigmoidf_(g0.x + x0.x);
            float fg = sigmoidf_(g0.y + x0.y);
            float gg = tanhf    (g0.z + x1.x);
            float og = sigmoidf_(g0.w + x1.y);
            creg0 = fg * creg0 + ig * gg;
            float hv0 = og * tanhf(creg0);

            ig = sigmoidf_(g1.x + x2.x);
            fg = sigmoidf_(g1.y + x2.y);
            gg = tanhf    (g1.z + x3.x);
            og = sigmoidf_(g1.w + x3.y);
            creg1 = fg * creg1 + ig * gg;
            float hv1 = og * tanhf(creg1);

            *reinterpret_cast<__half2*>(&g_hh[(s + 1) & 1][grow * HID + ub]) =
                __halves2half2(__float2half_rn(hv0), __float2half_rn(hv1));
        }

        // publish: h stores fenced per-thread, then block sync, then single flag store
        __threadfence();
        __syncthreads();
        if (tid == 0) *(volatile int*)&g_flag[myflag] = s + 1;
    }
}

// ---------------- decode (1024 threads, 8-way K split) ----------------
__global__ void lstm_decode(const float* __restrict__ W_dec, const float* __restrict__ b_dec,
                            float* __restrict__ out){
    __shared__ float wsh[NOUT * HID];
    __shared__ float lsh[NOUT * NBATCH];
    __shared__ float red[2 * NOUT];
    int tid = threadIdx.x;
    for (int i = tid; i < NOUT * HID; i += 1024) wsh[i] = W_dec[i];
    __syncthreads();
    int b = tid >> 3, kseg = tid & 7;
    const uint4* hp = reinterpret_cast<const uint4*>(&g_hh[0][b * HID + kseg * 128]);
    float a[4] = {0.f, 0.f, 0.f, 0.f};
    #pragma unroll 4
    for (int v = 0; v < 16; v++){
        uint4 pk = hp[v];
        const __half* h8 = reinterpret_cast<const __half*>(&pk);
        #pragma unroll
        for (int e = 0; e < 8; e++){
            float hv = __half2float(h8[e]);
            int kk = kseg * 128 + v * 8 + e;
            a[0] += hv * wsh[kk];
            a[1] += hv * wsh[HID + kk];
            a[2] += hv * wsh[2 * HID + kk];
            a[3] += hv * wsh[3 * HID + kk];
        }
    }
    #pragma unroll
    for (int o = 0; o < 4; o++){
        a[o] += __shfl_xor_sync(0xFFFFFFFFu, a[o], 1);
        a[o] += __shfl_xor_sync(0xFFFFFFFFu, a[o], 2);
        a[o] += __shfl_xor_sync(0xFFFFFFFFu, a[o], 4);
    }
    if (kseg == 0){
        #pragma unroll
        for (int o = 0; o < 4; o++) lsh[o * NBATCH + b] = a[o] + b_dec[o];
    }
    __syncthreads();
    if (tid < NOUT){
        int o = tid;
        float m = -1e30f;
        for (int j = 0; j < NBATCH; j++) m = fmaxf(m, lsh[o * NBATCH + j]);
        float sum = 0.0f;
        for (int j = 0; j < NBATCH; j++) sum += expf(lsh[o * NBATCH + j] - m);
        red[o] = m; red[NOUT + o] = sum;
    }
    __syncthreads();
    if (tid < NBATCH){
        #pragma unroll
        for (int o = 0; o < NOUT; o++)
            out[tid * NOUT + o] = expf(lsh[o * NBATCH + tid] - red[o]) / red[NOUT + o];
    }
}

// ---------------- launch ----------------
extern "C" void kernel_launch(void* const* d_in, const int* in_sizes, int n_in,
                              void* d_out, int out_size)
{
    const float* inputs = (const float*)d_in[0];
    const float* h0     = (const float*)d_in[1];
    const float* c0     = (const float*)d_in[2];
    const float* W_ih   = (const float*)d_in[3];
    const float* W_hh   = (const float*)d_in[4];
    const float* b_ih   = (const float*)d_in[5];
    const float* b_hh   = (const float*)d_in[6];
    const float* W_dec  = (const float*)d_in[7];
    const float* b_dec  = (const float*)d_in[8];
    float* out = (float*)d_out;

    cudaFuncSetAttribute(lstm_rec, cudaFuncAttributeMaxDynamicSharedMemorySize, DYN_B);
    cudaFuncSetAttribute(xproj_gemm, cudaFuncAttributeMaxDynamicSharedMemorySize, P1DYN);

    {
        int n8 = (S_LEN * NBATCH * IN_DIM) / 8;
        cvt_inputs<<<(n8 + 255) / 256, 256>>>(inputs);
        int nw = GDIM * (IN_DIM / 4);
        cvt_wih<<<(nw + 255) / 256, 256>>>(W_ih, b_ih, b_hh, h0);
    }

    dim3 g1(GDIM / BN, (S_LEN * NBATCH) / BM);   // 32 x 512
    xproj_gemm<<<g1, P1TH, P1DYN>>>();

    lstm_rec<<<PGRID, PTH, DYN_B>>>(W_hh, c0);

    lstm_decode<<<1, 1024>>>(W_dec, b_dec, out);
}

// round 13
// speedup vs baseline: 1.4950x; 1.1466x over previous
#include <cuda_runtime.h>
#include <cuda_bf16.h>
#include <cuda_fp16.h>
#include <math.h>
#include <stdint.h>

#define S_LEN   512
#define NBATCH  128
#define IN_DIM  512
#define HID     1024
#define GDIM    4096   // interleaved: col g -> gate g&3, unit g>>2
#define NOUT    4

// phase-1 tiling: 128x128 tiles, BK=64, 3-stage cp.async (R11-proven)
#define BM 128
#define BN 128
#define BKP 64
#define P1TH 256
#define P1STG_B 32768
#define P1DYN (3 * P1STG_B)

// recurrence: 128 CTAs = 2 row-halves x 64 col-tiles, each 64x64xK
// 4 warps x (32x32) warp tiles -> half the LDSM traffic of 16x16
#define PGRID 128
#define PTH 128
#define NCH 4                    // K chunks of 256
#define CHB 32768                // chunk: 64 rows x 512B
#define WB  131072               // W: 64 gate-cols x 2048B
#define OFF_W 0
#define OFF_A WB
#define DYN_B (WB + 3 * CHB)     // 229376

__device__ __half g_xp[(size_t)S_LEN * NBATCH * GDIM];   // x_proj (+bias), fp16
__device__ __half g_xh[(size_t)S_LEN * NBATCH * IN_DIM]; // inputs fp16
__device__ __half g_wih[(size_t)GDIM * IN_DIM];          // gathered W_ih fp16
__device__ float  g_bias[GDIM];                          // gathered b_ih+b_hh
__device__ __half g_hh[2][NBATCH * HID];                 // hidden fp16, dbl-buffered
__device__ int g_flag[PGRID * 32];                       // per-CTA step flag, 1 line each

__device__ __forceinline__ unsigned su32(const void* p){
    return (unsigned)__cvta_generic_to_shared(p);
}
__device__ __forceinline__ float fsig(float x){
    float e, r;
    asm("ex2.approx.f32 %0, %1;" : "=f"(e) : "f"(-x * 1.4426950408889634f));
    asm("rcp.approx.f32 %0, %1;" : "=f"(r) : "f"(1.0f + e));
    return r;
}
__device__ __forceinline__ float ftanh_(float x){
    float r;
    asm("tanh.approx.f32 %0, %1;" : "=f"(r) : "f"(x));
    return r;
}
__device__ __forceinline__ void cpasync16(unsigned saddr, const void* g){
    asm volatile("cp.async.cg.shared.global [%0], [%1], 16;" :: "r"(saddr), "l"(g));
}
#define CP_COMMIT() asm volatile("cp.async.commit_group;")
#define CP_WAIT(n)  asm volatile("cp.async.wait_group %0;" :: "n"(n))

__device__ __forceinline__ void ldmx4(unsigned* r, unsigned addr){
    asm volatile("ldmatrix.sync.aligned.m8n8.x4.shared.b16 {%0,%1,%2,%3}, [%4];"
        : "=r"(r[0]), "=r"(r[1]), "=r"(r[2]), "=r"(r[3]) : "r"(addr));
}
__device__ __forceinline__ void mma_f16(float* d, const unsigned* a, const unsigned* b){
    asm volatile("mma.sync.aligned.m16n8k16.row.col.f32.f16.f16.f32 "
        "{%0,%1,%2,%3},{%4,%5,%6,%7},{%8,%9},{%0,%1,%2,%3};"
        : "+f"(d[0]), "+f"(d[1]), "+f"(d[2]), "+f"(d[3])
        : "r"(a[0]), "r"(a[1]), "r"(a[2]), "r"(a[3]), "r"(b[0]), "r"(b[1]));
}

// warp-0 poll: chunk ch of the caller's half needs col-tiles [16ch,16ch+16) at flag >= tgt
__device__ __forceinline__ void flag_poll16(int ch, int tgt, int half, int lane){
    if (lane < 16){
        const volatile int* f = &g_flag[(((ch << 4) + lane) * 2 + half) * 32];
        while (*f < tgt) __nanosleep(64);
    }
    __syncwarp();
}

// ---------------- conversion pre-kernels ----------------
__global__ void cvt_inputs(const float* __restrict__ in){
    size_t i = (size_t)(blockIdx.x * blockDim.x + threadIdx.x) * 8;
    if (i < (size_t)S_LEN * NBATCH * IN_DIM){
        float4 v0 = *reinterpret_cast<const float4*>(in + i);
        float4 v1 = *reinterpret_cast<const float4*>(in + i + 4);
        __half2* d = reinterpret_cast<__half2*>(&g_xh[i]);
        d[0] = __floats2half2_rn(v0.x, v0.y);
        d[1] = __floats2half2_rn(v0.z, v0.w);
        d[2] = __floats2half2_rn(v1.x, v1.y);
        d[3] = __floats2half2_rn(v1.z, v1.w);
    }
}
__global__ void cvt_wih(const float* __restrict__ W_ih,
                        const float* __restrict__ b_ih, const float* __restrict__ b_hh,
                        const float* __restrict__ h0){
    int idx = blockIdx.x * blockDim.x + threadIdx.x;
    if (idx < GDIM * (IN_DIM / 4)){
        int g = idx >> 7;
        int c = (idx & 127) * 4;
        int r = (g & 3) * HID + (g >> 2);
        float4 v = *reinterpret_cast<const float4*>(W_ih + (size_t)r * IN_DIM + c);
        __half2* d = reinterpret_cast<__half2*>(&g_wih[(size_t)g * IN_DIM + c]);
        d[0] = __floats2half2_rn(v.x, v.y);
        d[1] = __floats2half2_rn(v.z, v.w);
        if (c == 0) g_bias[g] = b_ih[r] + b_hh[r];
    }
    if (idx < NBATCH * HID) g_hh[0][idx] = __float2half_rn(h0[idx]);
    if (idx < PGRID) g_flag[idx * 32] = 0;
}

// ---------------- phase 1: x_proj 128x128, 3-stage cp.async (R11-proven) ----------------
__global__ __launch_bounds__(P1TH)
void xproj_gemm()
{
    extern __shared__ __align__(1024) char p1s[];
    const int tid = threadIdx.x, lane = tid & 31, wid = tid >> 5;
    const int warp_m = wid & 3;
    const int warp_n = wid >> 2;
    const int m0 = blockIdx.y * BM, n0 = blockIdx.x * BN;
    const unsigned sbase = su32(p1s);

    float acc[2][4][2][4];
    #pragma unroll
    for (int a = 0; a < 2; a++)
        #pragma unroll
        for (int b = 0; b < 4; b++)
            #pragma unroll
            for (int c = 0; c < 2; c++)
                #pragma unroll
                for (int d = 0; d < 4; d++) acc[a][b][c][d] = 0.0f;

    int pr[8], pc[8], ppart[8];
    const __half* gsrc[8];
    #pragma unroll
    for (int i = 0; i < 8; i++){
        int idx = tid + i * P1TH;
        ppart[i] = idx >> 10;
        int w = idx & 1023;
        pr[i] = w >> 3;
        pc[i] = w & 7;
        gsrc[i] = ppart[i] ? (g_wih + (size_t)(n0 + pr[i]) * IN_DIM + pc[i] * 8)
                           : (g_xh  + (size_t)(m0 + pr[i]) * IN_DIM + pc[i] * 8);
    }

    #pragma unroll
    for (int st = 0; st < 2; st++){
        #pragma unroll
        for (int i = 0; i < 8; i++){
            unsigned dst = sbase + st * P1STG_B + ppart[i] * 16384
                         + pr[i] * 128 + ((pc[i] ^ (pr[i] & 7)) << 4);
            cpasync16(dst, gsrc[i] + st * BKP);
        }
        CP_COMMIT();
    }

    const int KIT = IN_DIM / BKP;
    for (int kt = 0; kt < KIT; kt++){
        if (kt + 1 < KIT) CP_WAIT(1); else CP_WAIT(0);
        __syncthreads();

        if (kt + 2 < KIT){
            int st = (kt + 2) % 3;
            #pragma unroll
            for (int i = 0; i < 8; i++){
                unsigned dst = sbase + st * P1STG_B + ppart[i] * 16384
                             + pr[i] * 128 + ((pc[i] ^ (pr[i] & 7)) << 4);
                cpasync16(dst, gsrc[i] + (kt + 2) * BKP);
            }
            CP_COMMIT();
        }

        const unsigned ab = sbase + (kt % 3) * P1STG_B;
        const unsigned bb = ab + 16384;
        #pragma unroll
        for (int kk = 0; kk < 4; kk++){
            const int lrow = lane & 15;
            const int cc = (kk * 16 + ((lane >> 4) << 3)) >> 3;
            unsigned ah[2][4];
            #pragma unroll
            for (int mt = 0; mt < 2; mt++){
                int r = warp_m * 32 + mt * 16 + lrow;
                ldmx4(ah[mt], ab + r * 128 + ((cc ^ (r & 7)) << 4));
            }
            #pragma unroll
            for (int nb = 0; nb < 4; nb++){
                int r = warp_n * 64 + nb * 16 + lrow;
                unsigned t4[4], b[2][2];
                ldmx4(t4, bb + r * 128 + ((cc ^ (r & 7)) << 4));
                b[0][0] = t4[0]; b[1][0] = t4[1]; b[0][1] = t4[2]; b[1][1] = t4[3];
                #pragma unroll
                for (int mt = 0; mt < 2; mt++)
                    #pragma unroll
                    for (int nt = 0; nt < 2; nt++)
                        mma_f16(acc[mt][nb][nt], ah[mt], b[nt]);
            }
        }
    }

    #pragma unroll
    for (int mt = 0; mt < 2; mt++)
        #pragma unroll
        for (int nb = 0; nb < 4; nb++)
            #pragma unroll
            for (int nt = 0; nt < 2; nt++)
                #pragma unroll
                for (int pp = 0; pp < 2; pp++){
                    int row = m0 + warp_m * 32 + mt * 16 + (lane >> 2) + 8 * pp;
                    int col = n0 + warp_n * 64 + nb * 16 + nt * 8 + 2 * (lane & 3);
                    float v0 = acc[mt][nb][nt][2 * pp]     + g_bias[col];
                    float v1 = acc[mt][nb][nt][2 * pp + 1] + g_bias[col + 1];
                    *reinterpret_cast<__half2*>(&g_xp[(size_t)row * GDIM + col]) =
                        __floats2half2_rn(v0, v1);
                }
}

// ---------------- persistent recurrence (4 warps, 32x32 warp tiles) ----------------
__device__ __forceinline__ void load_chunk(unsigned abase_st, const __half* hsrc,
                                           int m0, int kt, int tid){
    #pragma unroll
    for (int i = 0; i < 16; i++){
        int u = tid + i * PTH;
        int r = u >> 5;
        int c16 = u & 31;
        const __half* src = hsrc + (size_t)(m0 + r) * HID + kt * 256 + c16 * 8;
        unsigned dst = abase_st + r * 512 + ((((c16 ^ r) & 7) | (c16 & 24)) << 4);
        cpasync16(dst, src);
    }
}

__global__ __launch_bounds__(PTH, 1)
void lstm_rec(const float* __restrict__ W_hh, const float* __restrict__ c0)
{
    extern __shared__ __align__(1024) char dyn[];
    const int tid  = threadIdx.x;
    const int lane = tid & 31;
    const int wid  = tid >> 5;
    const int warp_m = wid & 1;     // 0..1 : 32 rows each
    const int warp_n = wid >> 1;    // 0..1 : 32 cols each
    const int half = blockIdx.x & 1;
    const int m0 = half * 64;
    const int n0 = (blockIdx.x >> 1) * 64;
    const int myflag = blockIdx.x * 32;
    const unsigned wbase = su32(dyn + OFF_W);
    const unsigned abase = su32(dyn + OFF_A);

    for (int idx = tid; idx < 64 * (HID / 8); idx += PTH){
        int j  = idx >> 7;
        int c8 = idx & 127;
        int c  = c8 * 8;
        int g  = n0 + j;
        const float* src = W_hh + (size_t)((g & 3) * HID + (g >> 2)) * HID + c;
        float4 v0 = *reinterpret_cast<const float4*>(src);
        float4 v1 = *reinterpret_cast<const float4*>(src + 4);
        int sc = (c8 & ~7) | ((c8 ^ j) & 7);
        __half2* d = reinterpret_cast<__half2*>(dyn + OFF_W + j * 2048 + (sc << 4));
        d[0] = __floats2half2_rn(v0.x, v0.y);
        d[1] = __floats2half2_rn(v0.z, v0.w);
        d[2] = __floats2half2_rn(v1.x, v1.y);
        d[3] = __floats2half2_rn(v1.z, v1.w);
    }

    // epilogue ownership: 128 threads, each 8 consecutive units of one row
    const int erow = tid >> 1;               // 0..63 local batch row
    const int q    = tid & 1;                // half of the 16 units
    const int grow = m0 + erow;
    const int ub   = (n0 >> 2) + q * 8;      // first unit (8 per thread)
    float creg[8];
    #pragma unroll
    for (int u = 0; u < 8; u++) creg[u] = c0[grow * HID + ub + u];
    __syncthreads();

    for (int s = 0; s < S_LEN; s++){
        const __half* hsrc = g_hh[s & 1];

        // prefetch x_proj segment (32 fp16 = 4 uint4)
        const __half* xpr = g_xp + ((size_t)s * NBATCH + grow) * GDIM + n0 + q * 32;
        uint4 xpk[4];
        #pragma unroll
        for (int i = 0; i < 4; i++)
            xpk[i] = *reinterpret_cast<const uint4*>(xpr + i * 8);

        float acc[2][4][4];   // [mt][bn*2+nt][4]
        #pragma unroll
        for (int a = 0; a < 2; a++)
            #pragma unroll
            for (int b = 0; b < 4; b++)
                #pragma unroll
                for (int k = 0; k < 4; k++) acc[a][b][k] = 0.0f;

        // wait for chunk 0+1 producers (col-tiles 0..31 of this half), then load
        if (wid == 0 && lane < 32){
            const volatile int* f = &g_flag[(lane * 2 + half) * 32];
            while (*f < s) __nanosleep(64);
        }
        __syncthreads();
        load_chunk(abase + 0 * CHB, hsrc, m0, 0, tid); CP_COMMIT();
        load_chunk(abase + 1 * CHB, hsrc, m0, 1, tid); CP_COMMIT();

        for (int kt = 0; kt < NCH; kt++){
            if (kt + 2 < NCH){
                if (wid == 0) flag_poll16(kt + 2, s, half, lane);
                __syncthreads();
                load_chunk(abase + ((kt + 2) % 3) * CHB, hsrc, m0, kt + 2, tid);
                CP_COMMIT();
                CP_WAIT(2);
            } else if (kt == NCH - 2){
                CP_WAIT(1);
            } else {
                CP_WAIT(0);
            }
            __syncthreads();

            const unsigned ab = abase + (kt % 3) * CHB;
            #pragma unroll
            for (int kkl = 0; kkl < 16; kkl++){
                const int lrow = lane & 15;
                const int koff = kkl * 16 + ((lane >> 4) << 3);
                const int c16  = koff >> 3;
                unsigned ah[2][4];
                #pragma unroll
                for (int mt = 0; mt < 2; mt++){
                    int r = warp_m * 32 + mt * 16 + lrow;
                    ldmx4(ah[mt], ab + r * 512 + ((((c16 ^ r) & 7) | (c16 & 24)) << 4));
                }
                #pragma unroll
                for (int bn = 0; bn < 2; bn++){
                    int r = warp_n * 32 + bn * 16 + lrow;
                    int c8 = (kt * 256 + koff) >> 3;
                    unsigned t4[4], b[2][2];
                    ldmx4(t4, wbase + r * 2048 + (((c8 & ~7) | ((c8 ^ r) & 7)) << 4));
                    b[0][0] = t4[0]; b[1][0] = t4[1]; b[0][1] = t4[2]; b[1][1] = t4[3];
                    #pragma unroll
                    for (int mt = 0; mt < 2; mt++)
                        #pragma unroll
                        for (int nt = 0; nt < 2; nt++)
                            mma_f16(acc[mt][bn * 2 + nt], ah[mt], b[nt]);
                }
            }
        }
        __syncthreads();           // all compute done before gates overwrite stage 0

        // stage gates (16KB in stage-0 buffer)
        float* gates = (float*)(dyn + OFF_A);
        #pragma unroll
        for (int mt = 0; mt < 2; mt++)
            #pragma unroll
            for (int bn = 0; bn < 2; bn++)
                #pragma unroll
                for (int nt = 0; nt < 2; nt++)
                    #pragma unroll
                    for (int pp = 0; pp < 2; pp++){
                        int row = warp_m * 32 + mt * 16 + (lane >> 2) + 8 * pp;
                        int col = warp_n * 32 + bn * 16 + nt * 8 + 2 * (lane & 3);
                        gates[row * 64 + col]     = acc[mt][bn * 2 + nt][2 * pp];
                        gates[row * 64 + col + 1] = acc[mt][bn * 2 + nt][2 * pp + 1];
                    }
        __syncthreads();

        {
            const float* gr = &gates[erow * 64 + q * 32];
            __half hbuf[8];
            #pragma unroll
            for (int u = 0; u < 8; u++){
                float4 gv = *reinterpret_cast<const float4*>(gr + u * 4);
                const __half2* xh2 = reinterpret_cast<const __half2*>(&xpk[u >> 1]);
                float2 xa = __half22float2(xh2[(u & 1) * 2]);
                float2 xb = __half22float2(xh2[(u & 1) * 2 + 1]);
                float ig = fsig  (gv.x + xa.x);
                float fg = fsig  (gv.y + xa.y);
                float gg = ftanh_(gv.z + xb.x);
                float og = fsig  (gv.w + xb.y);
                creg[u] = fg * creg[u] + ig * gg;
                hbuf[u] = __float2half_rn(og * ftanh_(creg[u]));
            }
            *reinterpret_cast<uint4*>(&g_hh[(s + 1) & 1][grow * HID + ub]) =
                *reinterpret_cast<uint4*>(hbuf);
        }

        // publish: h stores fenced, then block sync, then single flag store
        __threadfence();
        __syncthreads();
        if (tid == 0) *(volatile int*)&g_flag[myflag] = s + 1;
    }
}

// ---------------- decode (1024 threads, 8-way K split) ----------------
__global__ void lstm_decode(const float* __restrict__ W_dec, const float* __restrict__ b_dec,
                            float* __restrict__ out){
    __shared__ float wsh[NOUT * HID];
    __shared__ float lsh[NOUT * NBATCH];
    __shared__ float red[2 * NOUT];
    int tid = threadIdx.x;
    for (int i = tid; i < NOUT * HID; i += 1024) wsh[i] = W_dec[i];
    __syncthreads();
    int b = tid >> 3, kseg = tid & 7;
    const uint4* hp = reinterpret_cast<const uint4*>(&g_hh[0][b * HID + kseg * 128]);
    float a[4] = {0.f, 0.f, 0.f, 0.f};
    #pragma unroll 4
    for (int v = 0; v < 16; v++){
        uint4 pk = hp[v];
        const __half* h8 = reinterpret_cast<const __half*>(&pk);
        #pragma unroll
        for (int e = 0; e < 8; e++){
            float hv = __half2float(h8[e]);
            int kk = kseg * 128 + v * 8 + e;
            a[0] += hv * wsh[kk];
            a[1] += hv * wsh[HID + kk];
            a[2] += hv * wsh[2 * HID + kk];
            a[3] += hv * wsh[3 * HID + kk];
        }
    }
    #pragma unroll
    for (int o = 0; o < 4; o++){
        a[o] += __shfl_xor_sync(0xFFFFFFFFu, a[o], 1);
        a[o] += __shfl_xor_sync(0xFFFFFFFFu, a[o], 2);
        a[o] += __shfl_xor_sync(0xFFFFFFFFu, a[o], 4);
    }
    if (kseg == 0){
        #pragma unroll
        for (int o = 0; o < 4; o++) lsh[o * NBATCH + b] = a[o] + b_dec[o];
    }
    __syncthreads();
    if (tid < NOUT){
        int o = tid;
        float m = -1e30f;
        for (int j = 0; j < NBATCH; j++) m = fmaxf(m, lsh[o * NBATCH + j]);
        float sum = 0.0f;
        for (int j = 0; j < NBATCH; j++) sum += expf(lsh[o * NBATCH + j] - m);
        red[o] = m; red[NOUT + o] = sum;
    }
    __syncthreads();
    if (tid < NBATCH){
        #pragma unroll
        for (int o = 0; o < NOUT; o++)
            out[tid * NOUT + o] = expf(lsh[o * NBATCH + tid] - red[o]) / red[NOUT + o];
    }
}

// ---------------- launch ----------------
extern "C" void kernel_launch(void* const* d_in, const int* in_sizes, int n_in,
                              void* d_out, int out_size)
{
    const float* inputs = (const float*)d_in[0];
    const float* h0     = (const float*)d_in[1];
    const float* c0     = (const float*)d_in[2];
    const float* W_ih   = (const float*)d_in[3];
    const float* W_hh   = (const float*)d_in[4];
    const float* b_ih   = (const float*)d_in[5];
    const float* b_hh   = (const float*)d_in[6];
    const float* W_dec  = (const float*)d_in[7];
    const float* b_dec  = (const float*)d_in[8];
    float* out = (float*)d_out;

    cudaFuncSetAttribute(lstm_rec, cudaFuncAttributeMaxDynamicSharedMemorySize, DYN_B);
    cudaFuncSetAttribute(xproj_gemm, cudaFuncAttributeMaxDynamicSharedMemorySize, P1DYN);

    {
        int n8 = (S_LEN * NBATCH * IN_DIM) / 8;
        cvt_inputs<<<(n8 + 255) / 256, 256>>>(inputs);
        int nw = GDIM * (IN_DIM / 4);
        cvt_wih<<<(nw + 255) / 256, 256>>>(W_ih, b_ih, b_hh, h0);
    }

    dim3 g1(GDIM / BN, (S_LEN * NBATCH) / BM);   // 32 x 512
    xproj_gemm<<<g1, P1TH, P1DYN>>>();

    lstm_rec<<<PGRID, PTH, DYN_B>>>(W_hh, c0);

    lstm_decode<<<1, 1024>>>(W_dec, b_dec, out);
}

// round 14
// speedup vs baseline: 1.5292x; 1.0229x over previous
#include <cuda_runtime.h>
#include <cuda_bf16.h>
#include <cuda_fp16.h>
#include <math.h>
#include <stdint.h>

#define S_LEN   512
#define NBATCH  128
#define IN_DIM  512
#define HID     1024
#define GDIM    4096   // interleaved: col g -> gate g&3, unit g>>2
#define NOUT    4

// phase-1 tiling: 128x128 tiles, BK=64, 3-stage cp.async (R11-proven)
#define BM 128
#define BN 128
#define BKP 64
#define P1TH 256
#define P1STG_B 32768
#define P1DYN (3 * P1STG_B)

// recurrence: 128 CTAs = 2 row-halves x 64 col-tiles, each 64x64xK
// 8 warps = 2(m) x 2(n) x 2(k-split): 32x32 tiles, constant LDSM traffic
#define PGRID 128
#define PTH 256
#define NCH 4                    // K chunks of 256
#define CHB 32768                // chunk: 64 rows x 512B
#define WB  131072               // W: 64 gate-cols x 2048B
#define OFF_W 0
#define OFF_A WB
#define DYN_B (WB + 3 * CHB)     // 229376

__device__ __half g_xp[(size_t)S_LEN * NBATCH * GDIM];   // x_proj (+bias), fp16
__device__ __half g_xh[(size_t)S_LEN * NBATCH * IN_DIM]; // inputs fp16
__device__ __half g_wih[(size_t)GDIM * IN_DIM];          // gathered W_ih fp16
__device__ float  g_bias[GDIM];                          // gathered b_ih+b_hh
__device__ __half g_hh[2][NBATCH * HID];                 // hidden fp16, dbl-buffered
__device__ int g_flag[PGRID * 32];                       // per-CTA step flag, 1 line each

__device__ __forceinline__ unsigned su32(const void* p){
    return (unsigned)__cvta_generic_to_shared(p);
}
__device__ __forceinline__ float fsig(float x){
    float e, r;
    asm("ex2.approx.f32 %0, %1;" : "=f"(e) : "f"(-x * 1.4426950408889634f));
    asm("rcp.approx.f32 %0, %1;" : "=f"(r) : "f"(1.0f + e));
    return r;
}
__device__ __forceinline__ float ftanh_(float x){
    float r;
    asm("tanh.approx.f32 %0, %1;" : "=f"(r) : "f"(x));
    return r;
}
__device__ __forceinline__ void cpasync16(unsigned saddr, const void* g){
    asm volatile("cp.async.cg.shared.global [%0], [%1], 16;" :: "r"(saddr), "l"(g));
}
#define CP_COMMIT() asm volatile("cp.async.commit_group;")
#define CP_WAIT(n)  asm volatile("cp.async.wait_group %0;" :: "n"(n))

__device__ __forceinline__ void ldmx4(unsigned* r, unsigned addr){
    asm volatile("ldmatrix.sync.aligned.m8n8.x4.shared.b16 {%0,%1,%2,%3}, [%4];"
        : "=r"(r[0]), "=r"(r[1]), "=r"(r[2]), "=r"(r[3]) : "r"(addr));
}
__device__ __forceinline__ void mma_f16(float* d, const unsigned* a, const unsigned* b){
    asm volatile("mma.sync.aligned.m16n8k16.row.col.f32.f16.f16.f32 "
        "{%0,%1,%2,%3},{%4,%5,%6,%7},{%8,%9},{%0,%1,%2,%3};"
        : "+f"(d[0]), "+f"(d[1]), "+f"(d[2]), "+f"(d[3])
        : "r"(a[0]), "r"(a[1]), "r"(a[2]), "r"(a[3]), "r"(b[0]), "r"(b[1]));
}

// warp-0 poll: chunk ch of the caller's half needs col-tiles [16ch,16ch+16) at flag >= tgt
__device__ __forceinline__ void flag_poll16(int ch, int tgt, int half, int lane){
    if (lane < 16){
        const volatile int* f = &g_flag[(((ch << 4) + lane) * 2 + half) * 32];
        while (*f < tgt) __nanosleep(64);
    }
    __syncwarp();
}

// ---------------- conversion pre-kernels ----------------
__global__ void cvt_inputs(const float* __restrict__ in){
    size_t i = (size_t)(blockIdx.x * blockDim.x + threadIdx.x) * 8;
    if (i < (size_t)S_LEN * NBATCH * IN_DIM){
        float4 v0 = *reinterpret_cast<const float4*>(in + i);
        float4 v1 = *reinterpret_cast<const float4*>(in + i + 4);
        __half2* d = reinterpret_cast<__half2*>(&g_xh[i]);
        d[0] = __floats2half2_rn(v0.x, v0.y);
        d[1] = __floats2half2_rn(v0.z, v0.w);
        d[2] = __floats2half2_rn(v1.x, v1.y);
        d[3] = __floats2half2_rn(v1.z, v1.w);
    }
}
__global__ void cvt_wih(const float* __restrict__ W_ih,
                        const float* __restrict__ b_ih, const float* __restrict__ b_hh,
                        const float* __restrict__ h0){
    int idx = blockIdx.x * blockDim.x + threadIdx.x;
    if (idx < GDIM * (IN_DIM / 4)){
        int g = idx >> 7;
        int c = (idx & 127) * 4;
        int r = (g & 3) * HID + (g >> 2);
        float4 v = *reinterpret_cast<const float4*>(W_ih + (size_t)r * IN_DIM + c);
        __half2* d = reinterpret_cast<__half2*>(&g_wih[(size_t)g * IN_DIM + c]);
        d[0] = __floats2half2_rn(v.x, v.y);
        d[1] = __floats2half2_rn(v.z, v.w);
        if (c == 0) g_bias[g] = b_ih[r] + b_hh[r];
    }
    if (idx < NBATCH * HID) g_hh[0][idx] = __float2half_rn(h0[idx]);
    if (idx < PGRID) g_flag[idx * 32] = 0;
}

// ---------------- phase 1: x_proj 128x128, 3-stage cp.async (R11-proven) ----------------
__global__ __launch_bounds__(P1TH)
void xproj_gemm()
{
    extern __shared__ __align__(1024) char p1s[];
    const int tid = threadIdx.x, lane = tid & 31, wid = tid >> 5;
    const int warp_m = wid & 3;
    const int warp_n = wid >> 2;
    const int m0 = blockIdx.y * BM, n0 = blockIdx.x * BN;
    const unsigned sbase = su32(p1s);

    float acc[2][4][2][4];
    #pragma unroll
    for (int a = 0; a < 2; a++)
        #pragma unroll
        for (int b = 0; b < 4; b++)
            #pragma unroll
            for (int c = 0; c < 2; c++)
                #pragma unroll
                for (int d = 0; d < 4; d++) acc[a][b][c][d] = 0.0f;

    int pr[8], pc[8], ppart[8];
    const __half* gsrc[8];
    #pragma unroll
    for (int i = 0; i < 8; i++){
        int idx = tid + i * P1TH;
        ppart[i] = idx >> 10;
        int w = idx & 1023;
        pr[i] = w >> 3;
        pc[i] = w & 7;
        gsrc[i] = ppart[i] ? (g_wih + (size_t)(n0 + pr[i]) * IN_DIM + pc[i] * 8)
                           : (g_xh  + (size_t)(m0 + pr[i]) * IN_DIM + pc[i] * 8);
    }

    #pragma unroll
    for (int st = 0; st < 2; st++){
        #pragma unroll
        for (int i = 0; i < 8; i++){
            unsigned dst = sbase + st * P1STG_B + ppart[i] * 16384
                         + pr[i] * 128 + ((pc[i] ^ (pr[i] & 7)) << 4);
            cpasync16(dst, gsrc[i] + st * BKP);
        }
        CP_COMMIT();
    }

    const int KIT = IN_DIM / BKP;
    for (int kt = 0; kt < KIT; kt++){
        if (kt + 1 < KIT) CP_WAIT(1); else CP_WAIT(0);
        __syncthreads();

        if (kt + 2 < KIT){
            int st = (kt + 2) % 3;
            #pragma unroll
            for (int i = 0; i < 8; i++){
                unsigned dst = sbase + st * P1STG_B + ppart[i] * 16384
                             + pr[i] * 128 + ((pc[i] ^ (pr[i] & 7)) << 4);
                cpasync16(dst, gsrc[i] + (kt + 2) * BKP);
            }
            CP_COMMIT();
        }

        const unsigned ab = sbase + (kt % 3) * P1STG_B;
        const unsigned bb = ab + 16384;
        #pragma unroll
        for (int kk = 0; kk < 4; kk++){
            const int lrow = lane & 15;
            const int cc = (kk * 16 + ((lane >> 4) << 3)) >> 3;
            unsigned ah[2][4];
            #pragma unroll
            for (int mt = 0; mt < 2; mt++){
                int r = warp_m * 32 + mt * 16 + lrow;
                ldmx4(ah[mt], ab + r * 128 + ((cc ^ (r & 7)) << 4));
            }
            #pragma unroll
            for (int nb = 0; nb < 4; nb++){
                int r = warp_n * 64 + nb * 16 + lrow;
                unsigned t4[4], b[2][2];
                ldmx4(t4, bb + r * 128 + ((cc ^ (r & 7)) << 4));
                b[0][0] = t4[0]; b[1][0] = t4[1]; b[0][1] = t4[2]; b[1][1] = t4[3];
                #pragma unroll
                for (int mt = 0; mt < 2; mt++)
                    #pragma unroll
                    for (int nt = 0; nt < 2; nt++)
                        mma_f16(acc[mt][nb][nt], ah[mt], b[nt]);
            }
        }
    }

    #pragma unroll
    for (int mt = 0; mt < 2; mt++)
        #pragma unroll
        for (int nb = 0; nb < 4; nb++)
            #pragma unroll
            for (int nt = 0; nt < 2; nt++)
                #pragma unroll
                for (int pp = 0; pp < 2; pp++){
                    int row = m0 + warp_m * 32 + mt * 16 + (lane >> 2) + 8 * pp;
                    int col = n0 + warp_n * 64 + nb * 16 + nt * 8 + 2 * (lane & 3);
                    float v0 = acc[mt][nb][nt][2 * pp]     + g_bias[col];
                    float v1 = acc[mt][nb][nt][2 * pp + 1] + g_bias[col + 1];
                    *reinterpret_cast<__half2*>(&g_xp[(size_t)row * GDIM + col]) =
                        __floats2half2_rn(v0, v1);
                }
}

// ---------------- persistent recurrence (8 warps: 2m x 2n x 2k-split) ----------------
__device__ __forceinline__ void load_chunk(unsigned abase_st, const __half* hsrc,
                                           int m0, int kt, int tid){
    #pragma unroll
    for (int i = 0; i < 8; i++){
        int u = tid + i * PTH;
        int r = u >> 5;
        int c16 = u & 31;
        const __half* src = hsrc + (size_t)(m0 + r) * HID + kt * 256 + c16 * 8;
        unsigned dst = abase_st + r * 512 + ((((c16 ^ r) & 7) | (c16 & 24)) << 4);
        cpasync16(dst, src);
    }
}

__global__ __launch_bounds__(PTH, 1)
void lstm_rec(const float* __restrict__ W_hh, const float* __restrict__ c0)
{
    extern __shared__ __align__(1024) char dyn[];
    const int tid  = threadIdx.x;
    const int lane = tid & 31;
    const int wid  = tid >> 5;
    const int warp_m = wid & 1;          // 0..1 : 32 rows
    const int warp_n = (wid >> 1) & 1;   // 0..1 : 32 cols
    const int warp_k = wid >> 2;         // 0..1 : K half of each chunk
    const int half = blockIdx.x & 1;
    const int m0 = half * 64;
    const int n0 = (blockIdx.x >> 1) * 64;
    const int myflag = blockIdx.x * 32;
    const unsigned wbase = su32(dyn + OFF_W);
    const unsigned abase = su32(dyn + OFF_A);

    for (int idx = tid; idx < 64 * (HID / 8); idx += PTH){
        int j  = idx >> 7;
        int c8 = idx & 127;
        int c  = c8 * 8;
        int g  = n0 + j;
        const float* src = W_hh + (size_t)((g & 3) * HID + (g >> 2)) * HID + c;
        float4 v0 = *reinterpret_cast<const float4*>(src);
        float4 v1 = *reinterpret_cast<const float4*>(src + 4);
        int sc = (c8 & ~7) | ((c8 ^ j) & 7);
        __half2* d = reinterpret_cast<__half2*>(dyn + OFF_W + j * 2048 + (sc << 4));
        d[0] = __floats2half2_rn(v0.x, v0.y);
        d[1] = __floats2half2_rn(v0.z, v0.w);
        d[2] = __floats2half2_rn(v1.x, v1.y);
        d[3] = __floats2half2_rn(v1.z, v1.w);
    }

    // epilogue ownership: 256 threads, each 4 consecutive units of one row
    const int erow = tid >> 2;               // 0..63 local batch row
    const int q    = tid & 3;                // quarter of the 16 units
    const int grow = m0 + erow;
    const int ub   = (n0 >> 2) + q * 4;      // first unit (4 per thread)
    float creg[4];
    #pragma unroll
    for (int u = 0; u < 4; u++) creg[u] = c0[grow * HID + ub + u];
    __syncthreads();

    for (int s = 0; s < S_LEN; s++){
        const __half* hsrc = g_hh[s & 1];

        // prefetch x_proj segment (16 fp16 = 2 uint4)
        const __half* xpr = g_xp + ((size_t)s * NBATCH + grow) * GDIM + n0 + q * 16;
        uint4 xpk[2];
        xpk[0] = *reinterpret_cast<const uint4*>(xpr);
        xpk[1] = *reinterpret_cast<const uint4*>(xpr + 8);

        float acc[2][4][4];   // [mt][bn*2+nt][4] (partial over this warp's K half)
        #pragma unroll
        for (int a = 0; a < 2; a++)
            #pragma unroll
            for (int b = 0; b < 4; b++)
                #pragma unroll
                for (int k = 0; k < 4; k++) acc[a][b][k] = 0.0f;

        // wait for chunk 0+1 producers (col-tiles 0..31 of this half), then load
        if (wid == 0 && lane < 32){
            const volatile int* f = &g_flag[(lane * 2 + half) * 32];
            while (*f < s) __nanosleep(64);
        }
        __syncthreads();
        load_chunk(abase + 0 * CHB, hsrc, m0, 0, tid); CP_COMMIT();
        load_chunk(abase + 1 * CHB, hsrc, m0, 1, tid); CP_COMMIT();

        for (int kt = 0; kt < NCH; kt++){
            if (kt + 2 < NCH){
                if (wid == 0) flag_poll16(kt + 2, s, half, lane);
                __syncthreads();
                load_chunk(abase + ((kt + 2) % 3) * CHB, hsrc, m0, kt + 2, tid);
                CP_COMMIT();
                CP_WAIT(2);
            } else if (kt == NCH - 2){
                CP_WAIT(1);
            } else {
                CP_WAIT(0);
            }
            __syncthreads();

            const unsigned ab = abase + (kt % 3) * CHB;
            #pragma unroll
            for (int kkl = 0; kkl < 8; kkl++){
                const int lrow = lane & 15;
                const int koff = warp_k * 128 + kkl * 16 + ((lane >> 4) << 3);
                const int c16  = koff >> 3;
                unsigned ah[2][4];
                #pragma unroll
                for (int mt = 0; mt < 2; mt++){
                    int r = warp_m * 32 + mt * 16 + lrow;
                    ldmx4(ah[mt], ab + r * 512 + ((((c16 ^ r) & 7) | (c16 & 24)) << 4));
                }
                #pragma unroll
                for (int bn = 0; bn < 2; bn++){
                    int r = warp_n * 32 + bn * 16 + lrow;
                    int c8 = (kt * 256 + koff) >> 3;
                    unsigned t4[4], b[2][2];
                    ldmx4(t4, wbase + r * 2048 + (((c8 & ~7) | ((c8 ^ r) & 7)) << 4));
                    b[0][0] = t4[0]; b[1][0] = t4[1]; b[0][1] = t4[2]; b[1][1] = t4[3];
                    #pragma unroll
                    for (int mt = 0; mt < 2; mt++)
                        #pragma unroll
                        for (int nt = 0; nt < 2; nt++)
                            mma_f16(acc[mt][bn * 2 + nt], ah[mt], b[nt]);
                }
            }
        }
        __syncthreads();           // all compute done before gates overwrite stage 0

        // stage gate partials: warp_k==0 -> buffer 0, warp_k==1 -> buffer 1 (32KB total)
        float* gates = (float*)(dyn + OFF_A + warp_k * 16384);
        #pragma unroll
        for (int mt = 0; mt < 2; mt++)
            #pragma unroll
            for (int bn = 0; bn < 2; bn++)
                #pragma unroll
                for (int nt = 0; nt < 2; nt++)
                    #pragma unroll
                    for (int pp = 0; pp < 2; pp++){
                        int row = warp_m * 32 + mt * 16 + (lane >> 2) + 8 * pp;
                        int col = warp_n * 32 + bn * 16 + nt * 8 + 2 * (lane & 3);
                        gates[row * 64 + col]     = acc[mt][bn * 2 + nt][2 * pp];
                        gates[row * 64 + col + 1] = acc[mt][bn * 2 + nt][2 * pp + 1];
                    }
        __syncthreads();

        {
            const float* gr0 = (const float*)(dyn + OFF_A)         + erow * 64 + q * 16;
            const float* gr1 = (const float*)(dyn + OFF_A + 16384) + erow * 64 + q * 16;
            __half hbuf[4];
            #pragma unroll
            for (int u = 0; u < 4; u++){
                float4 ga = *reinterpret_cast<const float4*>(gr0 + u * 4);
                float4 gb = *reinterpret_cast<const float4*>(gr1 + u * 4);
                const __half2* xh2 = reinterpret_cast<const __half2*>(&xpk[u >> 1]);
                float2 xa = __half22float2(xh2[(u & 1) * 2]);
                float2 xb = __half22float2(xh2[(u & 1) * 2 + 1]);
                float ig = fsig  (ga.x + gb.x + xa.x);
                float fg = fsig  (ga.y + gb.y + xa.y);
                float gg = ftanh_(ga.z + gb.z + xb.x);
                float og = fsig  (ga.w + gb.w + xb.y);
                creg[u] = fg * creg[u] + ig * gg;
                hbuf[u] = __float2half_rn(og * ftanh_(creg[u]));
            }
            *reinterpret_cast<uint2*>(&g_hh[(s + 1) & 1][grow * HID + ub]) =
                *reinterpret_cast<uint2*>(hbuf);
        }

        // publish: h stores fenced, then block sync, then single flag store
        __threadfence();
        __syncthreads();
        if (tid == 0) *(volatile int*)&g_flag[myflag] = s + 1;
    }
}

// ---------------- decode (1024 threads, 8-way K split) ----------------
__global__ void lstm_decode(const float* __restrict__ W_dec, const float* __restrict__ b_dec,
                            float* __restrict__ out){
    __shared__ float wsh[NOUT * HID];
    __shared__ float lsh[NOUT * NBATCH];
    __shared__ float red[2 * NOUT];
    int tid = threadIdx.x;
    for (int i = tid; i < NOUT * HID; i += 1024) wsh[i] = W_dec[i];
    __syncthreads();
    int b = tid >> 3, kseg = tid & 7;
    const uint4* hp = reinterpret_cast<const uint4*>(&g_hh[0][b * HID + kseg * 128]);
    float a[4] = {0.f, 0.f, 0.f, 0.f};
    #pragma unroll 4
    for (int v = 0; v < 16; v++){
        uint4 pk = hp[v];
        const __half* h8 = reinterpret_cast<const __half*>(&pk);
        #pragma unroll
        for (int e = 0; e < 8; e++){
            float hv = __half2float(h8[e]);
            int kk = kseg * 128 + v * 8 + e;
            a[0] += hv * wsh[kk];
            a[1] += hv * wsh[HID + kk];
            a[2] += hv * wsh[2 * HID + kk];
            a[3] += hv * wsh[3 * HID + kk];
        }
    }
    #pragma unroll
    for (int o = 0; o < 4; o++){
        a[o] += __shfl_xor_sync(0xFFFFFFFFu, a[o], 1);
        a[o] += __shfl_xor_sync(0xFFFFFFFFu, a[o], 2);
        a[o] += __shfl_xor_sync(0xFFFFFFFFu, a[o], 4);
    }
    if (kseg == 0){
        #pragma unroll
        for (int o = 0; o < 4; o++) lsh[o * NBATCH + b] = a[o] + b_dec[o];
    }
    __syncthreads();
    if (tid < NOUT){
        int o = tid;
        float m = -1e30f;
        for (int j = 0; j < NBATCH; j++) m = fmaxf(m, lsh[o * NBATCH + j]);
        float sum = 0.0f;
        for (int j = 0; j < NBATCH; j++) sum += expf(lsh[o * NBATCH + j] - m);
        red[o] = m; red[NOUT + o] = sum;
    }
    __syncthreads();
    if (tid < NBATCH){
        #pragma unroll
        for (int o = 0; o < NOUT; o++)
            out[tid * NOUT + o] = expf(lsh[o * NBATCH + tid] - red[o]) / red[NOUT + o];
    }
}

// ---------------- launch ----------------
extern "C" void kernel_launch(void* const* d_in, const int* in_sizes, int n_in,
                              void* d_out, int out_size)
{
    const float* inputs = (const float*)d_in[0];
    const float* h0     = (const float*)d_in[1];
    const float* c0     = (const float*)d_in[2];
    const float* W_ih   = (const float*)d_in[3];
    const float* W_hh   = (const float*)d_in[4];
    const float* b_ih   = (const float*)d_in[5];
    const float* b_hh   = (const float*)d_in[6];
    const float* W_dec  = (const float*)d_in[7];
    const float* b_dec  = (const float*)d_in[8];
    float* out = (float*)d_out;

    cudaFuncSetAttribute(lstm_rec, cudaFuncAttributeMaxDynamicSharedMemorySize, DYN_B);
    cudaFuncSetAttribute(xproj_gemm, cudaFuncAttributeMaxDynamicSharedMemorySize, P1DYN);

    {
        int n8 = (S_LEN * NBATCH * IN_DIM) / 8;
        cvt_inputs<<<(n8 + 255) / 256, 256>>>(inputs);
        int nw = GDIM * (IN_DIM / 4);
        cvt_wih<<<(nw + 255) / 256, 256>>>(W_ih, b_ih, b_hh, h0);
    }

    dim3 g1(GDIM / BN, (S_LEN * NBATCH) / BM);   // 32 x 512
    xproj_gemm<<<g1, P1TH, P1DYN>>>();

    lstm_rec<<<PGRID, PTH, DYN_B>>>(W_hh, c0);

    lstm_decode<<<1, 1024>>>(W_dec, b_dec, out);
}